// round 9
// baseline (speedup 1.0000x reference)
#include <cuda_runtime.h>
#include <cuda_fp16.h>
#include <cuda_bf16.h>
#include <cstdint>

#define BATCH 16
#define HW 409600
#define HW4 102400
#define PB 100          // blocks per batch in pass1
#define CHUNK4 1024     // float4 elems per block
#define NT 256
#define NKC 5
#define EPSL 1e-6

// f16-derived p has low 13 float bits zero -> key = (bits>>13) - KOFF is lossless
#define KOFF 105472u    // 0x33800000 >> 13  (p = 2^-24, min positive f16)
#define NHB  24576      // keys span [0, 24575] for p in [2^-24, 1)
#define CH   24         // NHB / 1024

// ---------------- scratch (device globals; zero at module load) ------------
// Every kernel that consumes scratch re-zeroes it afterwards, so each graph
// replay starts from the same (all-zero) state. No zero kernel needed.
__device__ unsigned int g_hist1[BATCH][NHB];     // 1.6 MB
__device__ double g_sp[BATCH], g_sp2[BATCH], g_losstext[BATCH];
__device__ unsigned int g_npos[BATCH];
__device__ double g_ki[BATCH * NKC], g_kii[BATCH * NKC], g_ktt[BATCH * NKC];

// ---------------- helpers ----------------
// two sigmoids in one MUFU op: p = 0.5*tanh(x/2)+0.5 on f16x2
__device__ __forceinline__ __half2 htanh2(__half2 v) {
    unsigned u = *reinterpret_cast<unsigned*>(&v);
    unsigned r;
    asm("tanh.approx.f16x2 %0, %1;" : "=r"(r) : "r"(u));
    return *reinterpret_cast<__half2*>(&r);
}
__device__ __forceinline__ __half2 sig2(float x0, float x1) {
    const __half2 h05 = __half2half2(__float2half_rn(0.5f));
    __half2 h = __floats2half2_rn(x0, x1);
    h = __hmul2(h, h05);
    __half2 t = htanh2(h);
    return __hfma2(t, h05, h05);
}

// ---------------- pass1: single fused sweep over all 340 MB ---------------
__global__ void __launch_bounds__(NT) pass1_kernel(
    const float4* __restrict__ pred, const float4* __restrict__ gtt,
    const float4* __restrict__ gtk,  const float4* __restrict__ msk)
{
    __shared__ float sred[8][19];   // 19 to de-conflict banks
    int b = blockIdx.x / PB;
    int base4 = (blockIdx.x % PB) * CHUNK4;

    const float4* m4 = msk + (size_t)b * HW4;
    const float4* g4 = gtt + (size_t)b * HW4;
    const float4* p4 = pred + (size_t)b * 6 * HW4;   // channel 0 = text
    const float4* gk0 = gtk + (size_t)b * NKC * HW4;
    unsigned* __restrict__ h1 = &g_hist1[b][0];

    float sp = 0.f, sp2 = 0.f, np = 0.f;
    __half2 aint[NKC], asii[NKC], astt[NKC];
    const __half2 hz = __half2half2(__float2half_rn(0.0f));
    #pragma unroll
    for (int c = 0; c < NKC; c++) { aint[c] = hz; asii[c] = hz; astt[c] = hz; }

    #pragma unroll
    for (int i = 0; i < 4; i++) {
        int idx = base4 + threadIdx.x + i * NT;

        // ---- batch ALL 13 independent loads up-front (MLP=13) ----
        float4 mv = m4[idx];
        float4 gv = g4[idx];
        float4 pv = p4[idx];
        float4 pk[NKC], gk[NKC];
        #pragma unroll
        for (int c = 0; c < NKC; c++) pk[c] = p4[(size_t)(1 + c) * HW4 + idx];
        #pragma unroll
        for (int c = 0; c < NKC; c++) gk[c] = gk0[(size_t)c * HW4 + idx];

        // ---- text channel (f32: feeds OHEM histogram + dice numerator) ----
        __half2 tA = sig2(pv.x, pv.y);
        __half2 tB = sig2(pv.z, pv.w);
        float ps0 = __low2float(tA), ps1 = __high2float(tA);
        float ps2 = __low2float(tB), ps3 = __high2float(tB);
        #define PROC(COMP, PV)                                                    \
        {                                                                         \
            float m = mv.COMP, g = gv.COMP;                                       \
            float p = PV;                                                         \
            float pm = g * m;                                                     \
            float pp = p * pm;                                                    \
            np += pm; sp += pp; sp2 = fmaf(pp, pp, sp2);                          \
            if (m - g > 0.5f) {       /* negative: m=1 && g=0 */                  \
                unsigned bits = __float_as_uint(p);                               \
                unsigned key = bits >> 13;                                        \
                key = (key > KOFF) ? key - KOFF : 0u;                             \
                if (key >= NHB) key = NHB - 1u;                                   \
                atomicAdd(&h1[key], 1u);                                          \
            }                                                                     \
        }
        PROC(x, ps0) PROC(y, ps1) PROC(z, ps2) PROC(w, ps3)
        #undef PROC

        // ---- kernel dice channels, all half2 (m,g in {0,1}) ----
        __half2 mh01 = __floats2half2_rn(mv.x, mv.y);
        __half2 mh23 = __floats2half2_rn(mv.z, mv.w);
        #pragma unroll
        for (int c = 0; c < NKC; c++) {
            __half2 sA = sig2(pk[c].x, pk[c].y);
            __half2 sB = sig2(pk[c].z, pk[c].w);
            __half2 gA = __floats2half2_rn(gk[c].x, gk[c].y);
            __half2 gB = __floats2half2_rn(gk[c].z, gk[c].w);
            __half2 smA = __hmul2(sA, mh01);
            __half2 smB = __hmul2(sB, mh23);
            aint[c] = __hfma2(smA, gA, __hfma2(smB, gB, aint[c]));   // s*g*m
            asii[c] = __hfma2(smA, sA, __hfma2(smB, sB, asii[c]));   // s*s*m
            astt[c] = __hfma2(gA, mh01, __hfma2(gB, mh23, astt[c])); // g*m
        }
    }

    // ---- single-stage block reduction of 18 scalars ----
    float vals[18];
    vals[0] = np; vals[1] = sp; vals[2] = sp2;
    #pragma unroll
    for (int c = 0; c < NKC; c++) {
        vals[3 + 3 * c + 0] = __low2float(aint[c]) + __high2float(aint[c]);
        vals[3 + 3 * c + 1] = __low2float(asii[c]) + __high2float(asii[c]);
        vals[3 + 3 * c + 2] = __low2float(astt[c]) + __high2float(astt[c]);
    }
    #pragma unroll
    for (int j = 0; j < 18; j++) {
        #pragma unroll
        for (int o = 16; o; o >>= 1) vals[j] += __shfl_down_sync(0xFFFFFFFFu, vals[j], o);
    }
    int lane = threadIdx.x & 31, w = threadIdx.x >> 5;
    if (lane == 0) {
        #pragma unroll
        for (int j = 0; j < 18; j++) sred[w][j] = vals[j];
    }
    __syncthreads();
    int t = threadIdx.x;
    if (t < 18) {
        float s = 0.f;
        #pragma unroll
        for (int ww = 0; ww < 8; ww++) s += sred[ww][t];
        if (t == 0)      atomicAdd(&g_npos[b], (unsigned)(s + 0.5f));
        else if (t == 1) atomicAdd(&g_sp[b],  (double)s);
        else if (t == 2) atomicAdd(&g_sp2[b], (double)s);
        else {
            int j = t - 3, c = j / 3, r = j - 3 * c;
            int id = b * NKC + c;
            if (r == 0)      atomicAdd(&g_ki[id],  (double)s);
            else if (r == 1) atomicAdd(&g_kii[id], (double)s);
            else             atomicAdd(&g_ktt[id], (double)s);
        }
    }
}

// per-batch: OHEM select over exact-key histogram + hard-negative sum +
// loss_text; then restores its scratch (hist1, sp, sp2, npos) to zero.
__global__ void __launch_bounds__(1024) pass2_kernel() {
    int b = blockIdx.x;
    int t = threadIdx.x;
    __shared__ unsigned ccnt[1024];   // -> inclusive suffix counts
    __shared__ double   cw[1024];     // -> inclusive suffix of count*v^2
    __shared__ double   sHard;

    int base = t * CH;
    unsigned s = 0; double w = 0.0;
    #pragma unroll 4
    for (int j = 0; j < CH; j++) {
        unsigned c = g_hist1[b][base + j];
        if (c) {
            float v = __uint_as_float((unsigned)(base + j) + KOFF << 13);
            s += c; w += (double)c * (double)v * (double)v;
        }
    }
    ccnt[t] = s; cw[t] = w;
    __syncthreads();
    // inclusive suffix scan (Hillis-Steele)
    for (int off = 1; off < 1024; off <<= 1) {
        unsigned ca = (t + off < 1024) ? ccnt[t + off] : 0u;
        double   wa = (t + off < 1024) ? cw[t + off]   : 0.0;
        __syncthreads();
        ccnt[t] += ca; cw[t] += wa;
        __syncthreads();
    }
    unsigned nneg = ccnt[0];
    unsigned npos = g_npos[b];
    unsigned k = 3u * npos; if (k > nneg) k = nneg;
    if (t == 0) sHard = 0.0;
    __syncthreads();
    if (k > 0) {
        unsigned incl  = ccnt[t];
        unsigned above = (t < 1023) ? ccnt[t + 1] : 0u;
        if (above < k && incl >= k) {
            double wacc = (t < 1023) ? cw[t + 1] : 0.0;
            unsigned cum = above;
            for (int j = CH - 1; j >= 0; j--) {
                unsigned c = g_hist1[b][base + j];
                if (!c) continue;
                float v = __uint_as_float((unsigned)(base + j) + KOFF << 13);
                double v2 = (double)v * (double)v;
                if (cum + c >= k) { sHard = wacc + (double)(k - cum) * v2; break; }
                cum += c; wacc += (double)c * v2;
            }
        }
    }
    __syncthreads();
    if (t == 0) {
        double np = (double)npos;
        g_losstext[b] = 1.0 - 2.0 * g_sp[b] / (g_sp2[b] + sHard + np + EPSL);
        // restore per-batch scalars for next replay
        g_sp[b] = 0.0; g_sp2[b] = 0.0; g_npos[b] = 0u;
    }
    // restore histogram for next replay (all reads of hist are done above)
    #pragma unroll 4
    for (int j = 0; j < CH; j++) g_hist1[b][base + j] = 0u;
}

// parallel epilogue; restores dice accumulators + losstext to zero.
__global__ void __launch_bounds__(128) final_kernel(float* out) {
    __shared__ double sd[128];
    int t = threadIdx.x;
    double v = 0.0;
    if (t < BATCH * NKC) {
        v = 1.0 - 2.0 * g_ki[t] / (g_kii[t] + g_ktt[t] + EPSL);
        g_ki[t] = 0.0; g_kii[t] = 0.0; g_ktt[t] = 0.0;
    }
    sd[t] = v;
    __syncthreads();
    #pragma unroll
    for (int o = 64; o; o >>= 1) { if (t < o) sd[t] += sd[t + o]; __syncthreads(); }
    double lk = sd[0] / (double)(BATCH * NKC);
    __syncthreads();
    double lt_in = 0.0;
    if (t < BATCH) { lt_in = g_losstext[t]; g_losstext[t] = 0.0; }
    sd[t] = lt_in;
    __syncthreads();
    #pragma unroll
    for (int o = 64; o; o >>= 1) { if (t < o) sd[t] += sd[t + o]; __syncthreads(); }
    if (t == 0) {
        double lt = sd[0] / (double)BATCH;
        out[0] = (float)(lk + 0.5 * lt);
        out[1] = (float)lt;
        out[2] = (float)lk;
    }
}

// ---------------- launch ----------------
extern "C" void kernel_launch(void* const* d_in, const int* in_sizes, int n_in,
                              void* d_out, int out_size) {
    const float4* pred = (const float4*)d_in[0];
    const float4* gtt  = (const float4*)d_in[1];
    const float4* gtk  = (const float4*)d_in[2];
    const float4* msk  = (const float4*)d_in[3];
    float* out = (float*)d_out;

    pass1_kernel<<<BATCH * PB, NT>>>(pred, gtt, gtk, msk);
    pass2_kernel<<<BATCH, 1024>>>();
    final_kernel<<<1, 128>>>(out);
}

// round 10
// speedup vs baseline: 1.0173x; 1.0173x over previous
#include <cuda_runtime.h>
#include <cuda_fp16.h>
#include <cuda_bf16.h>
#include <cstdint>

#define BATCH 16
#define HW 409600
#define HW4 102400
#define PB 100          // blocks per batch per kernel
#define CHUNK4 1024     // float4 elems per block
#define NT 256
#define NKC 5
#define EPSL 1e-6

// f16-derived p has low 13 float bits zero -> key = (bits>>13) - KOFF is lossless
#define KOFF 105472u    // 0x33800000 >> 13  (p = 2^-24, min positive f16)
#define NHB  24576      // keys span [0, 24575] for p in [2^-24, 1)
#define CH   24         // NHB / 1024

// ---------------- scratch (device globals; zero at module load) ------------
// Consumers re-zero their scratch, so every graph replay starts all-zero.
__device__ unsigned int g_hist1[BATCH][NHB];     // 1.6 MB
__device__ double g_sp[BATCH], g_sp2[BATCH], g_losstext[BATCH];
__device__ unsigned int g_npos[BATCH];
__device__ double g_ki[BATCH * NKC], g_kii[BATCH * NKC], g_ktt[BATCH * NKC];

// ---------------- helpers ----------------
__device__ __forceinline__ __half2 htanh2(__half2 v) {
    unsigned u = *reinterpret_cast<unsigned*>(&v);
    unsigned r;
    asm("tanh.approx.f16x2 %0, %1;" : "=r"(r) : "r"(u));
    return *reinterpret_cast<__half2*>(&r);
}
__device__ __forceinline__ __half2 sig2(float x0, float x1) {
    const __half2 h05 = __half2half2(__float2half_rn(0.5f));
    __half2 h = __floats2half2_rn(x0, x1);
    h = __hmul2(h, h05);
    __half2 t = htanh2(h);
    return __hfma2(t, h05, h05);
}

// ---------------- dice kernel: pred ch1-5 x gt_kernels x mask --------------
// Slim streaming kernel: mask held as half2 (8 regs), 2 float4 live per step.
__global__ void __launch_bounds__(NT) dice_kernel(
    const float4* __restrict__ pred, const float4* __restrict__ gtk,
    const float4* __restrict__ msk)
{
    __shared__ float sred[8][16];
    int b = blockIdx.x / PB;
    int base4 = (blockIdx.x % PB) * CHUNK4;

    const float4* m4 = msk + (size_t)b * HW4;
    const float4* p4 = pred + (size_t)b * 6 * HW4;
    const float4* gk0 = gtk + (size_t)b * NKC * HW4;

    // mask: 16 px -> 8 half2 regs, reused by all 5 channels
    __half2 mh[4][2];
    #pragma unroll
    for (int i = 0; i < 4; i++) {
        float4 mv = m4[base4 + threadIdx.x + i * NT];
        mh[i][0] = __floats2half2_rn(mv.x, mv.y);
        mh[i][1] = __floats2half2_rn(mv.z, mv.w);
    }

    __half2 aint[NKC], asii[NKC], astt[NKC];
    const __half2 hz = __half2half2(__float2half_rn(0.0f));
    #pragma unroll
    for (int c = 0; c < NKC; c++) { aint[c] = hz; asii[c] = hz; astt[c] = hz; }

    #pragma unroll
    for (int c = 0; c < NKC; c++) {
        const float4* pc = p4 + (size_t)(1 + c) * HW4;
        const float4* gc = gk0 + (size_t)c * HW4;
        #pragma unroll
        for (int i = 0; i < 4; i++) {
            int idx = base4 + threadIdx.x + i * NT;
            float4 pk = pc[idx];
            float4 gk = gc[idx];
            __half2 sA = sig2(pk.x, pk.y);
            __half2 sB = sig2(pk.z, pk.w);
            __half2 gA = __floats2half2_rn(gk.x, gk.y);
            __half2 gB = __floats2half2_rn(gk.z, gk.w);
            __half2 smA = __hmul2(sA, mh[i][0]);
            __half2 smB = __hmul2(sB, mh[i][1]);
            aint[c] = __hfma2(smA, gA, __hfma2(smB, gB, aint[c]));      // s*g*m
            asii[c] = __hfma2(smA, sA, __hfma2(smB, sB, asii[c]));      // s*s*m
            astt[c] = __hfma2(gA, mh[i][0], __hfma2(gB, mh[i][1], astt[c])); // g*m
        }
    }

    // reduce 15 scalars: warp shfl -> smem -> threads 0..14 atomic
    float vals[15];
    #pragma unroll
    for (int c = 0; c < NKC; c++) {
        vals[3 * c + 0] = __low2float(aint[c]) + __high2float(aint[c]);
        vals[3 * c + 1] = __low2float(asii[c]) + __high2float(asii[c]);
        vals[3 * c + 2] = __low2float(astt[c]) + __high2float(astt[c]);
    }
    #pragma unroll
    for (int j = 0; j < 15; j++) {
        #pragma unroll
        for (int o = 16; o; o >>= 1) vals[j] += __shfl_down_sync(0xFFFFFFFFu, vals[j], o);
    }
    int lane = threadIdx.x & 31, w = threadIdx.x >> 5;
    if (lane == 0) {
        #pragma unroll
        for (int j = 0; j < 15; j++) sred[w][j] = vals[j];
    }
    __syncthreads();
    int t = threadIdx.x;
    if (t < 15) {
        float s = 0.f;
        #pragma unroll
        for (int ww = 0; ww < 8; ww++) s += sred[ww][t];
        int c = t / 3, r = t - 3 * c;
        int id = b * NKC + c;
        if (r == 0)      atomicAdd(&g_ki[id],  (double)s);
        else if (r == 1) atomicAdd(&g_kii[id], (double)s);
        else             atomicAdd(&g_ktt[id], (double)s);
    }
}

// ---------------- text kernel: pred ch0 x gt_text x mask + histogram ------
__global__ void __launch_bounds__(NT) text_kernel(
    const float4* __restrict__ pred, const float4* __restrict__ gtt,
    const float4* __restrict__ msk)
{
    __shared__ float sred[8][4];
    int b = blockIdx.x / PB;
    int base4 = (blockIdx.x % PB) * CHUNK4;

    const float4* m4 = msk + (size_t)b * HW4;
    const float4* g4 = gtt + (size_t)b * HW4;
    const float4* p4 = pred + (size_t)b * 6 * HW4;   // channel 0 = text
    unsigned* __restrict__ h1 = &g_hist1[b][0];

    float sp = 0.f, sp2 = 0.f, np = 0.f;

    #pragma unroll
    for (int i = 0; i < 4; i++) {
        int idx = base4 + threadIdx.x + i * NT;
        float4 mv = m4[idx];
        float4 gv = g4[idx];
        float4 pv = p4[idx];
        __half2 tA = sig2(pv.x, pv.y);
        __half2 tB = sig2(pv.z, pv.w);
        float ps0 = __low2float(tA), ps1 = __high2float(tA);
        float ps2 = __low2float(tB), ps3 = __high2float(tB);
        #define PROC(COMP, PV)                                                    \
        {                                                                         \
            float m = mv.COMP, g = gv.COMP;                                       \
            float p = PV;                                                         \
            float pm = g * m;                                                     \
            float pp = p * pm;                                                    \
            np += pm; sp += pp; sp2 = fmaf(pp, pp, sp2);                          \
            if (m - g > 0.5f) {       /* negative: m=1 && g=0 */                  \
                unsigned bits = __float_as_uint(p);                               \
                unsigned key = bits >> 13;                                        \
                key = (key > KOFF) ? key - KOFF : 0u;                             \
                if (key >= NHB) key = NHB - 1u;                                   \
                atomicAdd(&h1[key], 1u);                                          \
            }                                                                     \
        }
        PROC(x, ps0) PROC(y, ps1) PROC(z, ps2) PROC(w, ps3)
        #undef PROC
    }

    float vals[3] = {np, sp, sp2};
    #pragma unroll
    for (int j = 0; j < 3; j++) {
        #pragma unroll
        for (int o = 16; o; o >>= 1) vals[j] += __shfl_down_sync(0xFFFFFFFFu, vals[j], o);
    }
    int lane = threadIdx.x & 31, w = threadIdx.x >> 5;
    if (lane == 0) {
        #pragma unroll
        for (int j = 0; j < 3; j++) sred[w][j] = vals[j];
    }
    __syncthreads();
    int t = threadIdx.x;
    if (t < 3) {
        float s = 0.f;
        #pragma unroll
        for (int ww = 0; ww < 8; ww++) s += sred[ww][t];
        if (t == 0)      atomicAdd(&g_npos[b], (unsigned)(s + 0.5f));
        else if (t == 1) atomicAdd(&g_sp[b],  (double)s);
        else             atomicAdd(&g_sp2[b], (double)s);
    }
}

// per-batch: OHEM select over exact-key histogram + hard-negative sum +
// loss_text; restores its scratch (hist1, sp, sp2, npos) to zero.
__global__ void __launch_bounds__(1024) pass2_kernel() {
    int b = blockIdx.x;
    int t = threadIdx.x;
    __shared__ unsigned ccnt[1024];   // -> inclusive suffix counts
    __shared__ double   cw[1024];     // -> inclusive suffix of count*v^2
    __shared__ double   sHard;

    int base = t * CH;
    unsigned s = 0; double w = 0.0;
    #pragma unroll 4
    for (int j = 0; j < CH; j++) {
        unsigned c = g_hist1[b][base + j];
        if (c) {
            float v = __uint_as_float((unsigned)(base + j) + KOFF << 13);
            s += c; w += (double)c * (double)v * (double)v;
        }
    }
    ccnt[t] = s; cw[t] = w;
    __syncthreads();
    for (int off = 1; off < 1024; off <<= 1) {
        unsigned ca = (t + off < 1024) ? ccnt[t + off] : 0u;
        double   wa = (t + off < 1024) ? cw[t + off]   : 0.0;
        __syncthreads();
        ccnt[t] += ca; cw[t] += wa;
        __syncthreads();
    }
    unsigned nneg = ccnt[0];
    unsigned npos = g_npos[b];
    unsigned k = 3u * npos; if (k > nneg) k = nneg;
    if (t == 0) sHard = 0.0;
    __syncthreads();
    if (k > 0) {
        unsigned incl  = ccnt[t];
        unsigned above = (t < 1023) ? ccnt[t + 1] : 0u;
        if (above < k && incl >= k) {
            double wacc = (t < 1023) ? cw[t + 1] : 0.0;
            unsigned cum = above;
            for (int j = CH - 1; j >= 0; j--) {
                unsigned c = g_hist1[b][base + j];
                if (!c) continue;
                float v = __uint_as_float((unsigned)(base + j) + KOFF << 13);
                double v2 = (double)v * (double)v;
                if (cum + c >= k) { sHard = wacc + (double)(k - cum) * v2; break; }
                cum += c; wacc += (double)c * v2;
            }
        }
    }
    __syncthreads();
    if (t == 0) {
        double np = (double)npos;
        g_losstext[b] = 1.0 - 2.0 * g_sp[b] / (g_sp2[b] + sHard + np + EPSL);
        g_sp[b] = 0.0; g_sp2[b] = 0.0; g_npos[b] = 0u;
    }
    #pragma unroll 4
    for (int j = 0; j < CH; j++) g_hist1[b][base + j] = 0u;
}

// parallel epilogue; restores dice accumulators + losstext to zero.
__global__ void __launch_bounds__(128) final_kernel(float* out) {
    __shared__ double sd[128];
    int t = threadIdx.x;
    double v = 0.0;
    if (t < BATCH * NKC) {
        v = 1.0 - 2.0 * g_ki[t] / (g_kii[t] + g_ktt[t] + EPSL);
        g_ki[t] = 0.0; g_kii[t] = 0.0; g_ktt[t] = 0.0;
    }
    sd[t] = v;
    __syncthreads();
    #pragma unroll
    for (int o = 64; o; o >>= 1) { if (t < o) sd[t] += sd[t + o]; __syncthreads(); }
    double lk = sd[0] / (double)(BATCH * NKC);
    __syncthreads();
    double lt_in = 0.0;
    if (t < BATCH) { lt_in = g_losstext[t]; g_losstext[t] = 0.0; }
    sd[t] = lt_in;
    __syncthreads();
    #pragma unroll
    for (int o = 64; o; o >>= 1) { if (t < o) sd[t] += sd[t + o]; __syncthreads(); }
    if (t == 0) {
        double lt = sd[0] / (double)BATCH;
        out[0] = (float)(lk + 0.5 * lt);
        out[1] = (float)lt;
        out[2] = (float)lk;
    }
}

// ---------------- launch ----------------
extern "C" void kernel_launch(void* const* d_in, const int* in_sizes, int n_in,
                              void* d_out, int out_size) {
    const float4* pred = (const float4*)d_in[0];
    const float4* gtt  = (const float4*)d_in[1];
    const float4* gtk  = (const float4*)d_in[2];
    const float4* msk  = (const float4*)d_in[3];
    float* out = (float*)d_out;

    dice_kernel<<<BATCH * PB, NT>>>(pred, gtk, msk);
    text_kernel<<<BATCH * PB, NT>>>(pred, gtt, msk);
    pass2_kernel<<<BATCH, 1024>>>();
    final_kernel<<<1, 128>>>(out);
}

// round 11
// speedup vs baseline: 1.0206x; 1.0032x over previous
#include <cuda_runtime.h>
#include <cuda_fp16.h>
#include <cuda_bf16.h>
#include <cstdint>

#define BATCH 16
#define HW 409600
#define HW4 102400
#define NT 256
#define NKC 5
#define EPSL 1e-6

// text kernel tiling
#define PBT 100
#define CHUNK4T 1024
// dice kernel tiling (per-channel blocks)
#define PBD 200
#define CHUNK4D 512

// f16-derived p has low 13 float bits zero -> key = (bits>>13) - KOFF is lossless
#define KOFF 105472u    // 0x33800000 >> 13  (p = 2^-24, min positive f16)
#define NHB  24576      // keys span [0, 24575] for p in [2^-24, 1)
#define CH   24         // NHB / 1024

// ---------------- scratch (device globals; zero at module load) ------------
// Consumers re-zero their scratch (or fully overwrite it), so every graph
// replay starts from identical state.
__device__ unsigned int g_hist1[BATCH][NHB];        // 1.6 MB
__device__ unsigned int g_maskbits[BATCH * HW / 32]; // 0.82 MB, fully overwritten
__device__ double g_sp[BATCH], g_sp2[BATCH], g_losstext[BATCH];
__device__ unsigned int g_npos[BATCH];
__device__ double g_ki[BATCH * NKC], g_kii[BATCH * NKC], g_ktt[BATCH * NKC];

// ---------------- helpers ----------------
__device__ __forceinline__ __half2 htanh2(__half2 v) {
    unsigned u = *reinterpret_cast<unsigned*>(&v);
    unsigned r;
    asm("tanh.approx.f16x2 %0, %1;" : "=r"(r) : "r"(u));
    return *reinterpret_cast<__half2*>(&r);
}
__device__ __forceinline__ __half2 sig2(float x0, float x1) {
    const __half2 h05 = __half2half2(__float2half_rn(0.5f));
    __half2 h = __floats2half2_rn(x0, x1);
    h = __hmul2(h, h05);
    __half2 t = htanh2(h);
    return __hfma2(t, h05, h05);
}
// 2 mask bits -> half2 {b0?1:0, b1?1:0}
__device__ __forceinline__ __half2 bits2h2(unsigned nib, int b0, int b1) {
    unsigned r = ((nib >> b0) & 1u ? 0x3C00u : 0u) |
                 ((nib >> b1) & 1u ? 0x3C000000u : 0u);
    return *reinterpret_cast<__half2*>(&r);
}

// ---------------- mask pack: float mask -> 1 bit/px ----------------------
// 1024 blocks x 256 thr, stride 262144 divides 6553600 exactly (25 iters).
__global__ void __launch_bounds__(NT) pack_kernel(const float* __restrict__ msk) {
    const int NPX = BATCH * HW;
    int tid = blockIdx.x * NT + threadIdx.x;
    int stride = gridDim.x * NT;
    for (int px = tid; px < NPX; px += stride) {
        bool v = msk[px] > 0.5f;
        unsigned w = __ballot_sync(0xFFFFFFFFu, v);
        if ((threadIdx.x & 31) == 0) g_maskbits[px >> 5] = w;
    }
}

// ---------------- dice kernel: one (batch, channel, chunk) per block ------
// Slim: 3 half2 accumulators, 4 batched float4 loads + 2 bitmask words/iter.
__global__ void __launch_bounds__(NT, 6) dice_kernel(
    const float4* __restrict__ pred, const float4* __restrict__ gtk)
{
    __shared__ float sred[8][4];
    int blk = blockIdx.x;                 // BATCH*NKC*PBD
    int bc = blk / PBD, chunk = blk % PBD;
    int b = bc / NKC, c = bc % NKC;
    int base4 = chunk * CHUNK4D;

    const float4* pc = pred + ((size_t)b * 6 + 1 + c) * HW4;
    const float4* gc = gtk + ((size_t)b * NKC + c) * HW4;
    const unsigned* __restrict__ bm = g_maskbits + (size_t)b * (HW / 32);

    int idx0 = base4 + threadIdx.x;
    int idx1 = idx0 + NT;

    // batch all loads (MLP): 4x LDG.128 + 2x LDG.32
    float4 p0 = pc[idx0], p1 = pc[idx1];
    float4 g0 = gc[idx0], g1 = gc[idx1];
    unsigned n0 = (bm[idx0 >> 3] >> ((idx0 & 7) * 4)) & 0xFu;
    unsigned n1 = (bm[idx1 >> 3] >> ((idx1 & 7) * 4)) & 0xFu;

    __half2 aint, asii, astt;
    {
        __half2 mA = bits2h2(n0, 0, 1), mB = bits2h2(n0, 2, 3);
        __half2 sA = sig2(p0.x, p0.y), sB = sig2(p0.z, p0.w);
        __half2 gA = __floats2half2_rn(g0.x, g0.y), gB = __floats2half2_rn(g0.z, g0.w);
        __half2 smA = __hmul2(sA, mA), smB = __hmul2(sB, mB);
        aint = __hfma2(smA, gA, __hmul2(smB, gB));
        asii = __hfma2(smA, sA, __hmul2(smB, sB));
        astt = __hfma2(gA, mA, __hmul2(gB, mB));
    }
    {
        __half2 mA = bits2h2(n1, 0, 1), mB = bits2h2(n1, 2, 3);
        __half2 sA = sig2(p1.x, p1.y), sB = sig2(p1.z, p1.w);
        __half2 gA = __floats2half2_rn(g1.x, g1.y), gB = __floats2half2_rn(g1.z, g1.w);
        __half2 smA = __hmul2(sA, mA), smB = __hmul2(sB, mB);
        aint = __hfma2(smA, gA, __hfma2(smB, gB, aint));
        asii = __hfma2(smA, sA, __hfma2(smB, sB, asii));
        astt = __hfma2(gA, mA, __hfma2(gB, mB, astt));
    }

    float vals[3];
    vals[0] = __low2float(aint) + __high2float(aint);
    vals[1] = __low2float(asii) + __high2float(asii);
    vals[2] = __low2float(astt) + __high2float(astt);
    #pragma unroll
    for (int j = 0; j < 3; j++) {
        #pragma unroll
        for (int o = 16; o; o >>= 1) vals[j] += __shfl_down_sync(0xFFFFFFFFu, vals[j], o);
    }
    int lane = threadIdx.x & 31, w = threadIdx.x >> 5;
    if (lane == 0) {
        #pragma unroll
        for (int j = 0; j < 3; j++) sred[w][j] = vals[j];
    }
    __syncthreads();
    int t = threadIdx.x;
    if (t < 3) {
        float s = 0.f;
        #pragma unroll
        for (int ww = 0; ww < 8; ww++) s += sred[ww][t];
        int id = b * NKC + c;
        if (t == 0)      atomicAdd(&g_ki[id],  (double)s);
        else if (t == 1) atomicAdd(&g_kii[id], (double)s);
        else             atomicAdd(&g_ktt[id], (double)s);
    }
}

// ---------------- text kernel: pred ch0 x gt_text x mask + histogram ------
__global__ void __launch_bounds__(NT, 6) text_kernel(
    const float4* __restrict__ pred, const float4* __restrict__ gtt,
    const float4* __restrict__ msk)
{
    __shared__ float sred[8][4];
    int b = blockIdx.x / PBT;
    int base4 = (blockIdx.x % PBT) * CHUNK4T;

    const float4* m4 = msk + (size_t)b * HW4;
    const float4* g4 = gtt + (size_t)b * HW4;
    const float4* p4 = pred + (size_t)b * 6 * HW4;   // channel 0 = text
    unsigned* __restrict__ h1 = &g_hist1[b][0];

    float sp = 0.f, sp2 = 0.f, np = 0.f;

    #pragma unroll
    for (int i = 0; i < 4; i++) {
        int idx = base4 + threadIdx.x + i * NT;
        float4 mv = m4[idx];
        float4 gv = g4[idx];
        float4 pv = p4[idx];
        __half2 tA = sig2(pv.x, pv.y);
        __half2 tB = sig2(pv.z, pv.w);
        float ps0 = __low2float(tA), ps1 = __high2float(tA);
        float ps2 = __low2float(tB), ps3 = __high2float(tB);
        #define PROC(COMP, PV)                                                    \
        {                                                                         \
            float m = mv.COMP, g = gv.COMP;                                       \
            float p = PV;                                                         \
            float pm = g * m;                                                     \
            float pp = p * pm;                                                    \
            np += pm; sp += pp; sp2 = fmaf(pp, pp, sp2);                          \
            if (m - g > 0.5f) {       /* negative: m=1 && g=0 */                  \
                unsigned bits = __float_as_uint(p);                               \
                unsigned key = bits >> 13;                                        \
                key = (key > KOFF) ? key - KOFF : 0u;                             \
                if (key >= NHB) key = NHB - 1u;                                   \
                atomicAdd(&h1[key], 1u);                                          \
            }                                                                     \
        }
        PROC(x, ps0) PROC(y, ps1) PROC(z, ps2) PROC(w, ps3)
        #undef PROC
    }

    float vals[3] = {np, sp, sp2};
    #pragma unroll
    for (int j = 0; j < 3; j++) {
        #pragma unroll
        for (int o = 16; o; o >>= 1) vals[j] += __shfl_down_sync(0xFFFFFFFFu, vals[j], o);
    }
    int lane = threadIdx.x & 31, w = threadIdx.x >> 5;
    if (lane == 0) {
        #pragma unroll
        for (int j = 0; j < 3; j++) sred[w][j] = vals[j];
    }
    __syncthreads();
    int t = threadIdx.x;
    if (t < 3) {
        float s = 0.f;
        #pragma unroll
        for (int ww = 0; ww < 8; ww++) s += sred[ww][t];
        if (t == 0)      atomicAdd(&g_npos[b], (unsigned)(s + 0.5f));
        else if (t == 1) atomicAdd(&g_sp[b],  (double)s);
        else             atomicAdd(&g_sp2[b], (double)s);
    }
}

// per-batch: OHEM select over exact-key histogram + hard-negative sum +
// loss_text; restores its scratch (hist1, sp, sp2, npos) to zero.
__global__ void __launch_bounds__(1024) pass2_kernel() {
    int b = blockIdx.x;
    int t = threadIdx.x;
    __shared__ unsigned ccnt[1024];   // -> inclusive suffix counts
    __shared__ double   cw[1024];     // -> inclusive suffix of count*v^2
    __shared__ double   sHard;

    int base = t * CH;
    unsigned s = 0; double w = 0.0;
    #pragma unroll 4
    for (int j = 0; j < CH; j++) {
        unsigned c = g_hist1[b][base + j];
        if (c) {
            float v = __uint_as_float((unsigned)(base + j) + KOFF << 13);
            s += c; w += (double)c * (double)v * (double)v;
        }
    }
    ccnt[t] = s; cw[t] = w;
    __syncthreads();
    for (int off = 1; off < 1024; off <<= 1) {
        unsigned ca = (t + off < 1024) ? ccnt[t + off] : 0u;
        double   wa = (t + off < 1024) ? cw[t + off]   : 0.0;
        __syncthreads();
        ccnt[t] += ca; cw[t] += wa;
        __syncthreads();
    }
    unsigned nneg = ccnt[0];
    unsigned npos = g_npos[b];
    unsigned k = 3u * npos; if (k > nneg) k = nneg;
    if (t == 0) sHard = 0.0;
    __syncthreads();
    if (k > 0) {
        unsigned incl  = ccnt[t];
        unsigned above = (t < 1023) ? ccnt[t + 1] : 0u;
        if (above < k && incl >= k) {
            double wacc = (t < 1023) ? cw[t + 1] : 0.0;
            unsigned cum = above;
            for (int j = CH - 1; j >= 0; j--) {
                unsigned c = g_hist1[b][base + j];
                if (!c) continue;
                float v = __uint_as_float((unsigned)(base + j) + KOFF << 13);
                double v2 = (double)v * (double)v;
                if (cum + c >= k) { sHard = wacc + (double)(k - cum) * v2; break; }
                cum += c; wacc += (double)c * v2;
            }
        }
    }
    __syncthreads();
    if (t == 0) {
        double np = (double)npos;
        g_losstext[b] = 1.0 - 2.0 * g_sp[b] / (g_sp2[b] + sHard + np + EPSL);
        g_sp[b] = 0.0; g_sp2[b] = 0.0; g_npos[b] = 0u;
    }
    #pragma unroll 4
    for (int j = 0; j < CH; j++) g_hist1[b][base + j] = 0u;
}

// parallel epilogue; restores dice accumulators + losstext to zero.
__global__ void __launch_bounds__(128) final_kernel(float* out) {
    __shared__ double sd[128];
    int t = threadIdx.x;
    double v = 0.0;
    if (t < BATCH * NKC) {
        v = 1.0 - 2.0 * g_ki[t] / (g_kii[t] + g_ktt[t] + EPSL);
        g_ki[t] = 0.0; g_kii[t] = 0.0; g_ktt[t] = 0.0;
    }
    sd[t] = v;
    __syncthreads();
    #pragma unroll
    for (int o = 64; o; o >>= 1) { if (t < o) sd[t] += sd[t + o]; __syncthreads(); }
    double lk = sd[0] / (double)(BATCH * NKC);
    __syncthreads();
    double lt_in = 0.0;
    if (t < BATCH) { lt_in = g_losstext[t]; g_losstext[t] = 0.0; }
    sd[t] = lt_in;
    __syncthreads();
    #pragma unroll
    for (int o = 64; o; o >>= 1) { if (t < o) sd[t] += sd[t + o]; __syncthreads(); }
    if (t == 0) {
        double lt = sd[0] / (double)BATCH;
        out[0] = (float)(lk + 0.5 * lt);
        out[1] = (float)lt;
        out[2] = (float)lk;
    }
}

// ---------------- launch ----------------
extern "C" void kernel_launch(void* const* d_in, const int* in_sizes, int n_in,
                              void* d_out, int out_size) {
    const float4* pred = (const float4*)d_in[0];
    const float4* gtt  = (const float4*)d_in[1];
    const float4* gtk  = (const float4*)d_in[2];
    const float4* msk  = (const float4*)d_in[3];
    float* out = (float*)d_out;

    pack_kernel<<<1024, NT>>>((const float*)d_in[3]);
    dice_kernel<<<BATCH * NKC * PBD, NT>>>(pred, gtk);
    text_kernel<<<BATCH * PBT, NT>>>(pred, gtt, msk);
    pass2_kernel<<<BATCH, 1024>>>();
    final_kernel<<<1, 128>>>(out);
}

// round 12
// speedup vs baseline: 1.0696x; 1.0480x over previous
#include <cuda_runtime.h>
#include <cuda_fp16.h>
#include <cuda_bf16.h>
#include <cstdint>

#define BATCH 16
#define HW 409600
#define HW4 102400
#define NT 256
#define NKC 5
#define EPSL 1e-6

// text kernel tiling
#define PBT 100
#define CHUNK4T 1024
// dice kernel tiling (per-channel blocks)
#define PBD 100
#define CHUNK4D 1024

// f16-derived p has low 13 float bits zero -> key = (bits>>13) - KOFF is lossless
#define KOFF 105472u    // 0x33800000 >> 13  (p = 2^-24, min positive f16)
#define NHB  24576      // keys span [0, 24575] for p in [2^-24, 1)
#define CH   24         // NHB / 1024

// ---------------- scratch (device globals; zero at module load) ------------
// hist1 is cleared by pack_kernel each replay (before text_kernel fills it).
// Scalars are reset by their consumers. Every replay starts from zero state.
__device__ unsigned int g_hist1[BATCH][NHB];         // 1.6 MB
__device__ unsigned int g_maskbits[BATCH * HW / 32]; // 0.82 MB, fully overwritten
__device__ double g_sp[BATCH], g_sp2[BATCH], g_losstext[BATCH];
__device__ unsigned int g_npos[BATCH];
__device__ double g_ki[BATCH * NKC], g_kii[BATCH * NKC], g_ktt[BATCH * NKC];

// ---------------- helpers ----------------
__device__ __forceinline__ __half2 htanh2(__half2 v) {
    unsigned u = *reinterpret_cast<unsigned*>(&v);
    unsigned r;
    asm("tanh.approx.f16x2 %0, %1;" : "=r"(r) : "r"(u));
    return *reinterpret_cast<__half2*>(&r);
}
__device__ __forceinline__ __half2 sig2(float x0, float x1) {
    const __half2 h05 = __half2half2(__float2half_rn(0.5f));
    __half2 h = __floats2half2_rn(x0, x1);
    h = __hmul2(h, h05);
    __half2 t = htanh2(h);
    return __hfma2(t, h05, h05);
}
// 2 mask bits -> half2 {b0?1:0, b1?1:0}
__device__ __forceinline__ __half2 bits2h2(unsigned nib, int b0, int b1) {
    unsigned r = ((nib >> b0) & 1u ? 0x3C00u : 0u) |
                 ((nib >> b1) & 1u ? 0x3C000000u : 0u);
    return *reinterpret_cast<__half2*>(&r);
}

// ---------------- pack: float mask -> 1 bit/px, and clear hist1 ----------
__global__ void __launch_bounds__(NT) pack_kernel(const float* __restrict__ msk) {
    const int NPX = BATCH * HW;
    int tid = blockIdx.x * NT + threadIdx.x;
    int stride = gridDim.x * NT;
    for (int px = tid; px < NPX; px += stride) {
        bool v = msk[px] > 0.5f;
        unsigned w = __ballot_sync(0xFFFFFFFFu, v);
        if ((threadIdx.x & 31) == 0) g_maskbits[px >> 5] = w;
    }
    // coalesced grid-stride clear of the histogram (runs before text_kernel)
    unsigned* h1 = &g_hist1[0][0];
    const int NHTOT = BATCH * NHB;
    for (int i = tid; i < NHTOT; i += stride) h1[i] = 0u;
}

// ---------------- dice kernel: one (batch, channel, chunk) per block ------
// Slim: 3 half2 accumulators; 2 batched groups of (2 pk + 2 gk) float4 loads.
__global__ void __launch_bounds__(NT, 6) dice_kernel(
    const float4* __restrict__ pred, const float4* __restrict__ gtk)
{
    __shared__ float sred[8][4];
    int blk = blockIdx.x;                 // BATCH*NKC*PBD
    int bc = blk / PBD, chunk = blk % PBD;
    int b = bc / NKC, c = bc % NKC;
    int base4 = chunk * CHUNK4D;

    const float4* pc = pred + ((size_t)b * 6 + 1 + c) * HW4;
    const float4* gc = gtk + ((size_t)b * NKC + c) * HW4;
    const unsigned* __restrict__ bm = g_maskbits + (size_t)b * (HW / 32);

    const __half2 hz = __half2half2(__float2half_rn(0.0f));
    __half2 aint = hz, asii = hz, astt = hz;

    #pragma unroll
    for (int it = 0; it < 2; it++) {
        int idx0 = base4 + threadIdx.x + it * 2 * NT;
        int idx1 = idx0 + NT;
        // batch loads (MLP): 4x LDG.128 + 2x LDG.32
        float4 p0 = pc[idx0], p1 = pc[idx1];
        float4 g0 = gc[idx0], g1 = gc[idx1];
        unsigned n0 = (bm[idx0 >> 3] >> ((idx0 & 7) * 4)) & 0xFu;
        unsigned n1 = (bm[idx1 >> 3] >> ((idx1 & 7) * 4)) & 0xFu;
        {
            __half2 mA = bits2h2(n0, 0, 1), mB = bits2h2(n0, 2, 3);
            __half2 sA = sig2(p0.x, p0.y), sB = sig2(p0.z, p0.w);
            __half2 gA = __floats2half2_rn(g0.x, g0.y), gB = __floats2half2_rn(g0.z, g0.w);
            __half2 smA = __hmul2(sA, mA), smB = __hmul2(sB, mB);
            aint = __hfma2(smA, gA, __hfma2(smB, gB, aint));
            asii = __hfma2(smA, sA, __hfma2(smB, sB, asii));
            astt = __hfma2(gA, mA, __hfma2(gB, mB, astt));
        }
        {
            __half2 mA = bits2h2(n1, 0, 1), mB = bits2h2(n1, 2, 3);
            __half2 sA = sig2(p1.x, p1.y), sB = sig2(p1.z, p1.w);
            __half2 gA = __floats2half2_rn(g1.x, g1.y), gB = __floats2half2_rn(g1.z, g1.w);
            __half2 smA = __hmul2(sA, mA), smB = __hmul2(sB, mB);
            aint = __hfma2(smA, gA, __hfma2(smB, gB, aint));
            asii = __hfma2(smA, sA, __hfma2(smB, sB, asii));
            astt = __hfma2(gA, mA, __hfma2(gB, mB, astt));
        }
    }

    float vals[3];
    vals[0] = __low2float(aint) + __high2float(aint);
    vals[1] = __low2float(asii) + __high2float(asii);
    vals[2] = __low2float(astt) + __high2float(astt);
    #pragma unroll
    for (int j = 0; j < 3; j++) {
        #pragma unroll
        for (int o = 16; o; o >>= 1) vals[j] += __shfl_down_sync(0xFFFFFFFFu, vals[j], o);
    }
    int lane = threadIdx.x & 31, w = threadIdx.x >> 5;
    if (lane == 0) {
        #pragma unroll
        for (int j = 0; j < 3; j++) sred[w][j] = vals[j];
    }
    __syncthreads();
    int t = threadIdx.x;
    if (t < 3) {
        float s = 0.f;
        #pragma unroll
        for (int ww = 0; ww < 8; ww++) s += sred[ww][t];
        int id = b * NKC + c;
        if (t == 0)      atomicAdd(&g_ki[id],  (double)s);
        else if (t == 1) atomicAdd(&g_kii[id], (double)s);
        else             atomicAdd(&g_ktt[id], (double)s);
    }
}

// ---------------- text kernel: pred ch0 x gt_text x mask + histogram ------
__global__ void __launch_bounds__(NT, 6) text_kernel(
    const float4* __restrict__ pred, const float4* __restrict__ gtt,
    const float4* __restrict__ msk)
{
    __shared__ float sred[8][4];
    int b = blockIdx.x / PBT;
    int base4 = (blockIdx.x % PBT) * CHUNK4T;

    const float4* m4 = msk + (size_t)b * HW4;
    const float4* g4 = gtt + (size_t)b * HW4;
    const float4* p4 = pred + (size_t)b * 6 * HW4;   // channel 0 = text
    unsigned* __restrict__ h1 = &g_hist1[b][0];

    float sp = 0.f, sp2 = 0.f, np = 0.f;

    #pragma unroll
    for (int i = 0; i < 4; i++) {
        int idx = base4 + threadIdx.x + i * NT;
        float4 mv = m4[idx];
        float4 gv = g4[idx];
        float4 pv = p4[idx];
        __half2 tA = sig2(pv.x, pv.y);
        __half2 tB = sig2(pv.z, pv.w);
        float ps0 = __low2float(tA), ps1 = __high2float(tA);
        float ps2 = __low2float(tB), ps3 = __high2float(tB);
        #define PROC(COMP, PV)                                                    \
        {                                                                         \
            float m = mv.COMP, g = gv.COMP;                                       \
            float p = PV;                                                         \
            float pm = g * m;                                                     \
            float pp = p * pm;                                                    \
            np += pm; sp += pp; sp2 = fmaf(pp, pp, sp2);                          \
            if (m - g > 0.5f) {       /* negative: m=1 && g=0 */                  \
                unsigned bits = __float_as_uint(p);                               \
                unsigned key = bits >> 13;                                        \
                key = (key > KOFF) ? key - KOFF : 0u;                             \
                if (key >= NHB) key = NHB - 1u;                                   \
                atomicAdd(&h1[key], 1u);                                          \
            }                                                                     \
        }
        PROC(x, ps0) PROC(y, ps1) PROC(z, ps2) PROC(w, ps3)
        #undef PROC
    }

    float vals[3] = {np, sp, sp2};
    #pragma unroll
    for (int j = 0; j < 3; j++) {
        #pragma unroll
        for (int o = 16; o; o >>= 1) vals[j] += __shfl_down_sync(0xFFFFFFFFu, vals[j], o);
    }
    int lane = threadIdx.x & 31, w = threadIdx.x >> 5;
    if (lane == 0) {
        #pragma unroll
        for (int j = 0; j < 3; j++) sred[w][j] = vals[j];
    }
    __syncthreads();
    int t = threadIdx.x;
    if (t < 3) {
        float s = 0.f;
        #pragma unroll
        for (int ww = 0; ww < 8; ww++) s += sred[ww][t];
        if (t == 0)      atomicAdd(&g_npos[b], (unsigned)(s + 0.5f));
        else if (t == 1) atomicAdd(&g_sp[b],  (double)s);
        else             atomicAdd(&g_sp2[b], (double)s);
    }
}

// per-batch: OHEM select over exact-key histogram + hard-negative sum +
// loss_text. Read-only on hist1 (pack_kernel clears it next replay);
// resets only the tiny per-batch scalars.
__global__ void __launch_bounds__(1024) pass2_kernel() {
    int b = blockIdx.x;
    int t = threadIdx.x;
    __shared__ unsigned ccnt[1024];   // -> inclusive suffix counts
    __shared__ double   cw[1024];     // -> inclusive suffix of count*v^2
    __shared__ double   sHard;

    int base = t * CH;
    unsigned s = 0; double w = 0.0;
    #pragma unroll 4
    for (int j = 0; j < CH; j++) {
        unsigned c = g_hist1[b][base + j];
        if (c) {
            float v = __uint_as_float((unsigned)(base + j) + KOFF << 13);
            s += c; w += (double)c * (double)v * (double)v;
        }
    }
    ccnt[t] = s; cw[t] = w;
    __syncthreads();
    for (int off = 1; off < 1024; off <<= 1) {
        unsigned ca = (t + off < 1024) ? ccnt[t + off] : 0u;
        double   wa = (t + off < 1024) ? cw[t + off]   : 0.0;
        __syncthreads();
        ccnt[t] += ca; cw[t] += wa;
        __syncthreads();
    }
    unsigned nneg = ccnt[0];
    unsigned npos = g_npos[b];
    unsigned k = 3u * npos; if (k > nneg) k = nneg;
    if (t == 0) sHard = 0.0;
    __syncthreads();
    if (k > 0) {
        unsigned incl  = ccnt[t];
        unsigned above = (t < 1023) ? ccnt[t + 1] : 0u;
        if (above < k && incl >= k) {
            double wacc = (t < 1023) ? cw[t + 1] : 0.0;
            unsigned cum = above;
            for (int j = CH - 1; j >= 0; j--) {
                unsigned c = g_hist1[b][base + j];
                if (!c) continue;
                float v = __uint_as_float((unsigned)(base + j) + KOFF << 13);
                double v2 = (double)v * (double)v;
                if (cum + c >= k) { sHard = wacc + (double)(k - cum) * v2; break; }
                cum += c; wacc += (double)c * v2;
            }
        }
    }
    __syncthreads();
    if (t == 0) {
        double np = (double)npos;
        g_losstext[b] = 1.0 - 2.0 * g_sp[b] / (g_sp2[b] + sHard + np + EPSL);
        g_sp[b] = 0.0; g_sp2[b] = 0.0; g_npos[b] = 0u;
    }
}

// parallel epilogue; restores dice accumulators + losstext to zero.
__global__ void __launch_bounds__(128) final_kernel(float* out) {
    __shared__ double sd[128];
    int t = threadIdx.x;
    double v = 0.0;
    if (t < BATCH * NKC) {
        v = 1.0 - 2.0 * g_ki[t] / (g_kii[t] + g_ktt[t] + EPSL);
        g_ki[t] = 0.0; g_kii[t] = 0.0; g_ktt[t] = 0.0;
    }
    sd[t] = v;
    __syncthreads();
    #pragma unroll
    for (int o = 64; o; o >>= 1) { if (t < o) sd[t] += sd[t + o]; __syncthreads(); }
    double lk = sd[0] / (double)(BATCH * NKC);
    __syncthreads();
    double lt_in = 0.0;
    if (t < BATCH) { lt_in = g_losstext[t]; g_losstext[t] = 0.0; }
    sd[t] = lt_in;
    __syncthreads();
    #pragma unroll
    for (int o = 64; o; o >>= 1) { if (t < o) sd[t] += sd[t + o]; __syncthreads(); }
    if (t == 0) {
        double lt = sd[0] / (double)BATCH;
        out[0] = (float)(lk + 0.5 * lt);
        out[1] = (float)lt;
        out[2] = (float)lk;
    }
}

// ---------------- launch ----------------
extern "C" void kernel_launch(void* const* d_in, const int* in_sizes, int n_in,
                              void* d_out, int out_size) {
    const float4* pred = (const float4*)d_in[0];
    const float4* gtt  = (const float4*)d_in[1];
    const float4* gtk  = (const float4*)d_in[2];
    const float4* msk  = (const float4*)d_in[3];
    float* out = (float*)d_out;

    pack_kernel<<<1024, NT>>>((const float*)d_in[3]);
    dice_kernel<<<BATCH * NKC * PBD, NT>>>(pred, gtk);
    text_kernel<<<BATCH * PBT, NT>>>(pred, gtt, msk);
    pass2_kernel<<<BATCH, 1024>>>();
    final_kernel<<<1, 128>>>(out);
}

// round 13
// speedup vs baseline: 1.2138x; 1.1348x over previous
#include <cuda_runtime.h>
#include <cuda_fp16.h>
#include <cuda_bf16.h>
#include <cstdint>

#define BATCH 16
#define HW 409600
#define HW4 102400
#define NT 256
#define NKC 5
#define EPSL 1e-6

// text kernel tiling
#define PBT 100
#define CHUNK4T 1024
// dice kernel tiling (per-channel blocks)
#define PBD 100
#define CHUNK4D 1024

// f16-derived p has low 13 float bits zero -> key = (bits>>13) - KOFF is lossless
#define KOFF 105472u    // 0x33800000 >> 13  (p = 2^-24, min positive f16)
#define NHB  24576      // keys span [0, 24575] for p in [2^-24, 1)
#define CH   24         // NHB / 1024

// ---------------- scratch (device globals; zero at module load) ------------
// hist1 is cleared by pack_kernel each replay (before text_kernel fills it).
// Scalars are reset by their consumers. Every replay starts from zero state.
__device__ unsigned int g_hist1[BATCH][NHB];         // 1.6 MB
__device__ unsigned int g_maskbits[BATCH * HW / 32]; // 0.82 MB, fully overwritten
__device__ double g_sp[BATCH], g_sp2[BATCH], g_losstext[BATCH];
__device__ unsigned int g_npos[BATCH];
__device__ double g_ki[BATCH * NKC], g_kii[BATCH * NKC], g_ktt[BATCH * NKC];
__device__ unsigned int g_done;                      // last-block-done counter

// ---------------- helpers ----------------
__device__ __forceinline__ __half2 htanh2(__half2 v) {
    unsigned u = *reinterpret_cast<unsigned*>(&v);
    unsigned r;
    asm("tanh.approx.f16x2 %0, %1;" : "=r"(r) : "r"(u));
    return *reinterpret_cast<__half2*>(&r);
}
__device__ __forceinline__ __half2 sig2(float x0, float x1) {
    const __half2 h05 = __half2half2(__float2half_rn(0.5f));
    __half2 h = __floats2half2_rn(x0, x1);
    h = __hmul2(h, h05);
    __half2 t = htanh2(h);
    return __hfma2(t, h05, h05);
}
// 2 mask bits -> half2 {b0?1:0, b1?1:0}
__device__ __forceinline__ __half2 bits2h2(unsigned nib, int b0, int b1) {
    unsigned r = ((nib >> b0) & 1u ? 0x3C00u : 0u) |
                 ((nib >> b1) & 1u ? 0x3C000000u : 0u);
    return *reinterpret_cast<__half2*>(&r);
}
__device__ __forceinline__ float key2float(unsigned key) {
    return __uint_as_float((key + KOFF) << 13);
}

// ---------------- pack: float mask -> 1 bit/px, and clear hist1 ----------
__global__ void __launch_bounds__(NT) pack_kernel(const float* __restrict__ msk) {
    const int NPX = BATCH * HW;
    int tid = blockIdx.x * NT + threadIdx.x;
    int stride = gridDim.x * NT;
    for (int px = tid; px < NPX; px += stride) {
        bool v = msk[px] > 0.5f;
        unsigned w = __ballot_sync(0xFFFFFFFFu, v);
        if ((threadIdx.x & 31) == 0) g_maskbits[px >> 5] = w;
    }
    // coalesced grid-stride clear of the histogram (runs before text_kernel)
    unsigned* h1 = &g_hist1[0][0];
    const int NHTOT = BATCH * NHB;
    for (int i = tid; i < NHTOT; i += stride) h1[i] = 0u;
}

// ---------------- dice kernel: one (batch, channel, chunk) per block ------
__global__ void __launch_bounds__(NT, 6) dice_kernel(
    const float4* __restrict__ pred, const float4* __restrict__ gtk)
{
    __shared__ float sred[8][4];
    int blk = blockIdx.x;                 // BATCH*NKC*PBD
    int bc = blk / PBD, chunk = blk % PBD;
    int b = bc / NKC, c = bc % NKC;
    int base4 = chunk * CHUNK4D;

    const float4* pc = pred + ((size_t)b * 6 + 1 + c) * HW4;
    const float4* gc = gtk + ((size_t)b * NKC + c) * HW4;
    const unsigned* __restrict__ bm = g_maskbits + (size_t)b * (HW / 32);

    const __half2 hz = __half2half2(__float2half_rn(0.0f));
    __half2 aint = hz, asii = hz, astt = hz;

    #pragma unroll
    for (int it = 0; it < 2; it++) {
        int idx0 = base4 + threadIdx.x + it * 2 * NT;
        int idx1 = idx0 + NT;
        float4 p0 = pc[idx0], p1 = pc[idx1];
        float4 g0 = gc[idx0], g1 = gc[idx1];
        unsigned n0 = (bm[idx0 >> 3] >> ((idx0 & 7) * 4)) & 0xFu;
        unsigned n1 = (bm[idx1 >> 3] >> ((idx1 & 7) * 4)) & 0xFu;
        {
            __half2 mA = bits2h2(n0, 0, 1), mB = bits2h2(n0, 2, 3);
            __half2 sA = sig2(p0.x, p0.y), sB = sig2(p0.z, p0.w);
            __half2 gA = __floats2half2_rn(g0.x, g0.y), gB = __floats2half2_rn(g0.z, g0.w);
            __half2 smA = __hmul2(sA, mA), smB = __hmul2(sB, mB);
            aint = __hfma2(smA, gA, __hfma2(smB, gB, aint));
            asii = __hfma2(smA, sA, __hfma2(smB, sB, asii));
            astt = __hfma2(gA, mA, __hfma2(gB, mB, astt));
        }
        {
            __half2 mA = bits2h2(n1, 0, 1), mB = bits2h2(n1, 2, 3);
            __half2 sA = sig2(p1.x, p1.y), sB = sig2(p1.z, p1.w);
            __half2 gA = __floats2half2_rn(g1.x, g1.y), gB = __floats2half2_rn(g1.z, g1.w);
            __half2 smA = __hmul2(sA, mA), smB = __hmul2(sB, mB);
            aint = __hfma2(smA, gA, __hfma2(smB, gB, aint));
            asii = __hfma2(smA, sA, __hfma2(smB, sB, asii));
            astt = __hfma2(gA, mA, __hfma2(gB, mB, astt));
        }
    }

    float vals[3];
    vals[0] = __low2float(aint) + __high2float(aint);
    vals[1] = __low2float(asii) + __high2float(asii);
    vals[2] = __low2float(astt) + __high2float(astt);
    #pragma unroll
    for (int j = 0; j < 3; j++) {
        #pragma unroll
        for (int o = 16; o; o >>= 1) vals[j] += __shfl_down_sync(0xFFFFFFFFu, vals[j], o);
    }
    int lane = threadIdx.x & 31, w = threadIdx.x >> 5;
    if (lane == 0) {
        #pragma unroll
        for (int j = 0; j < 3; j++) sred[w][j] = vals[j];
    }
    __syncthreads();
    int t = threadIdx.x;
    if (t < 3) {
        float s = 0.f;
        #pragma unroll
        for (int ww = 0; ww < 8; ww++) s += sred[ww][t];
        int id = b * NKC + c;
        if (t == 0)      atomicAdd(&g_ki[id],  (double)s);
        else if (t == 1) atomicAdd(&g_kii[id], (double)s);
        else             atomicAdd(&g_ktt[id], (double)s);
    }
}

// ---------------- text kernel: pred ch0 x gt_text x mask + histogram ------
__global__ void __launch_bounds__(NT, 6) text_kernel(
    const float4* __restrict__ pred, const float4* __restrict__ gtt,
    const float4* __restrict__ msk)
{
    __shared__ float sred[8][4];
    int b = blockIdx.x / PBT;
    int base4 = (blockIdx.x % PBT) * CHUNK4T;

    const float4* m4 = msk + (size_t)b * HW4;
    const float4* g4 = gtt + (size_t)b * HW4;
    const float4* p4 = pred + (size_t)b * 6 * HW4;   // channel 0 = text
    unsigned* __restrict__ h1 = &g_hist1[b][0];

    float sp = 0.f, sp2 = 0.f, np = 0.f;

    #pragma unroll
    for (int i = 0; i < 4; i++) {
        int idx = base4 + threadIdx.x + i * NT;
        float4 mv = m4[idx];
        float4 gv = g4[idx];
        float4 pv = p4[idx];
        __half2 tA = sig2(pv.x, pv.y);
        __half2 tB = sig2(pv.z, pv.w);
        float ps0 = __low2float(tA), ps1 = __high2float(tA);
        float ps2 = __low2float(tB), ps3 = __high2float(tB);
        #define PROC(COMP, PV)                                                    \
        {                                                                         \
            float m = mv.COMP, g = gv.COMP;                                       \
            float p = PV;                                                         \
            float pm = g * m;                                                     \
            float pp = p * pm;                                                    \
            np += pm; sp += pp; sp2 = fmaf(pp, pp, sp2);                          \
            if (m - g > 0.5f) {       /* negative: m=1 && g=0 */                  \
                unsigned bits = __float_as_uint(p);                               \
                unsigned key = bits >> 13;                                        \
                key = (key > KOFF) ? key - KOFF : 0u;                             \
                if (key >= NHB) key = NHB - 1u;                                   \
                atomicAdd(&h1[key], 1u);                                          \
            }                                                                     \
        }
        PROC(x, ps0) PROC(y, ps1) PROC(z, ps2) PROC(w, ps3)
        #undef PROC
    }

    float vals[3] = {np, sp, sp2};
    #pragma unroll
    for (int j = 0; j < 3; j++) {
        #pragma unroll
        for (int o = 16; o; o >>= 1) vals[j] += __shfl_down_sync(0xFFFFFFFFu, vals[j], o);
    }
    int lane = threadIdx.x & 31, w = threadIdx.x >> 5;
    if (lane == 0) {
        #pragma unroll
        for (int j = 0; j < 3; j++) sred[w][j] = vals[j];
    }
    __syncthreads();
    int t = threadIdx.x;
    if (t < 3) {
        float s = 0.f;
        #pragma unroll
        for (int ww = 0; ww < 8; ww++) s += sred[ww][t];
        if (t == 0)      atomicAdd(&g_npos[b], (unsigned)(s + 0.5f));
        else if (t == 1) atomicAdd(&g_sp[b],  (double)s);
        else             atomicAdd(&g_sp2[b], (double)s);
    }
}

// ---------------- pass2: OHEM select + loss_text; last block does epilogue -
__global__ void __launch_bounds__(1024) pass2_kernel(float* __restrict__ out) {
    int b = blockIdx.x;
    int t = threadIdx.x;
    int lane = t & 31, wid = t >> 5;

    __shared__ unsigned sCntW[32];    // warp total counts
    __shared__ double   sWW[32];      // warp total weights
    __shared__ unsigned sCntA[32];    // count suffix strictly above warp w
    __shared__ double   sWA[32];      // weight suffix strictly above warp w
    __shared__ unsigned sTotal;
    __shared__ double   sHard;
    __shared__ int      sLast;
    __shared__ double   sd[128];

    // per-thread: 24 buckets, counts kept in registers, weight in fp32
    unsigned cnt[CH];
    int base = t * CH;
    unsigned s = 0; float wf = 0.f;
    #pragma unroll
    for (int j = 0; j < CH; j++) {
        unsigned c = g_hist1[b][base + j];
        cnt[j] = c;
        float v = key2float(base + j);
        s += c;
        wf = fmaf((float)c, v * v, wf);
    }
    double w = (double)wf;

    // warp-level inclusive suffix scan (thread t gets sum over lanes >= lane)
    unsigned sv = s; double wv = w;
    #pragma unroll
    for (int off = 1; off < 32; off <<= 1) {
        unsigned s2 = __shfl_down_sync(0xFFFFFFFFu, sv, off);
        double   w2 = __shfl_down_sync(0xFFFFFFFFu, wv, off);
        if (lane + off < 32) { sv += s2; wv += w2; }
    }
    if (lane == 0) { sCntW[wid] = sv; sWW[wid] = wv; }   // warp totals
    __syncthreads();
    // warp 0 scans the 32 warp totals (suffix), publishes "strictly above" sums
    if (wid == 0) {
        unsigned a = sCntW[lane]; double aw = sWW[lane];
        unsigned ai = a; double awi = aw;
        #pragma unroll
        for (int off = 1; off < 32; off <<= 1) {
            unsigned s2 = __shfl_down_sync(0xFFFFFFFFu, ai, off);
            double   w2 = __shfl_down_sync(0xFFFFFFFFu, awi, off);
            if (lane + off < 32) { ai += s2; awi += w2; }
        }
        sCntA[lane] = ai - a;     // suffix strictly above warp 'lane'
        sWA[lane]   = awi - aw;
        if (lane == 0) { sTotal = ai; sHard = 0.0; }
    }
    __syncthreads();

    unsigned nneg = sTotal;
    unsigned npos = g_npos[b];
    unsigned k = 3u * npos; if (k > nneg) k = nneg;

    // thread's inclusive suffix and strictly-above values
    unsigned incl = sv + sCntA[wid];
    unsigned above = incl - s;
    double wincl = wv + sWA[wid];
    double wabove = wincl - w;

    if (k > 0 && above < k && incl >= k) {
        // boundary thread: walk own 24 buckets high -> low (register array)
        double wacc = wabove;
        unsigned cum = above;
        bool done = false;
        #pragma unroll
        for (int j = CH - 1; j >= 0; j--) {
            if (!done) {
                unsigned c = cnt[j];
                float v = key2float(base + j);
                double v2 = (double)v * (double)v;
                if (cum + c >= k) { sHard = wacc + (double)(k - cum) * v2; done = true; }
                else { cum += c; wacc += (double)c * v2; }
            }
        }
    }
    __syncthreads();

    if (t == 0) {
        double np = (double)npos;
        g_losstext[b] = 1.0 - 2.0 * g_sp[b] / (g_sp2[b] + sHard + np + EPSL);
        g_sp[b] = 0.0; g_sp2[b] = 0.0; g_npos[b] = 0u;
        __threadfence();
        sLast = (atomicAdd(&g_done, 1u) == BATCH - 1);
    }
    __syncthreads();

    // last finishing block computes the final 3 outputs (dice sums were
    // written by dice_kernel, which completed before pass2 launched)
    if (sLast) {
        double v = 0.0;
        if (t < BATCH * NKC) {
            v = 1.0 - 2.0 * g_ki[t] / (g_kii[t] + g_ktt[t] + EPSL);
            g_ki[t] = 0.0; g_kii[t] = 0.0; g_ktt[t] = 0.0;
        }
        if (t < 128) sd[t] = v;
        __syncthreads();
        #pragma unroll
        for (int o = 64; o; o >>= 1) { if (t < o) sd[t] += sd[t + o]; __syncthreads(); }
        double lk = sd[0] / (double)(BATCH * NKC);
        __syncthreads();
        double lt_in = 0.0;
        if (t < BATCH) { lt_in = g_losstext[t]; g_losstext[t] = 0.0; }
        if (t < 128) sd[t] = lt_in;
        __syncthreads();
        #pragma unroll
        for (int o = 64; o; o >>= 1) { if (t < o) sd[t] += sd[t + o]; __syncthreads(); }
        if (t == 0) {
            double lt = sd[0] / (double)BATCH;
            out[0] = (float)(lk + 0.5 * lt);
            out[1] = (float)lt;
            out[2] = (float)lk;
            g_done = 0u;   // reset for next replay
        }
    }
}

// ---------------- launch ----------------
extern "C" void kernel_launch(void* const* d_in, const int* in_sizes, int n_in,
                              void* d_out, int out_size) {
    const float4* pred = (const float4*)d_in[0];
    const float4* gtt  = (const float4*)d_in[1];
    const float4* gtk  = (const float4*)d_in[2];
    const float4* msk  = (const float4*)d_in[3];
    float* out = (float*)d_out;

    pack_kernel<<<1024, NT>>>((const float*)d_in[3]);
    dice_kernel<<<BATCH * NKC * PBD, NT>>>(pred, gtk);
    text_kernel<<<BATCH * PBT, NT>>>(pred, gtt, msk);
    pass2_kernel<<<BATCH, 1024>>>(out);
}

// round 14
// speedup vs baseline: 1.2362x; 1.0184x over previous
#include <cuda_runtime.h>
#include <cuda_fp16.h>
#include <cuda_bf16.h>
#include <cstdint>

#define BATCH 16
#define HW 409600
#define HW4 102400
#define NT 256
#define NKC 5
#define EPSL 1e-6

// text kernel tiling
#define PBT 100
#define CHUNK4T 1024
// dice kernel tiling (per-channel blocks)
#define PBD 50
#define CHUNK4D 2048

// f16-derived p has low 13 float bits zero -> key = (bits>>13) - KOFF is lossless
#define KOFF 105472u    // 0x33800000 >> 13  (p = 2^-24, min positive f16)
#define NHB  24576      // keys span [0, 24575] for p in [2^-24, 1)
#define CH   24         // NHB / 1024

// ---------------- scratch (device globals; zero at module load) ------------
__device__ unsigned int g_hist1[BATCH][NHB];         // 1.6 MB
__device__ unsigned int g_maskbits[BATCH * HW / 32]; // 0.82 MB, fully overwritten
__device__ double g_sp[BATCH], g_sp2[BATCH], g_losstext[BATCH];
__device__ unsigned int g_npos[BATCH];
__device__ double g_ki[BATCH * NKC], g_kii[BATCH * NKC], g_ktt[BATCH * NKC];
__device__ unsigned int g_done;                      // last-block-done counter

// ---------------- helpers ----------------
__device__ __forceinline__ __half2 htanh2(__half2 v) {
    unsigned u = *reinterpret_cast<unsigned*>(&v);
    unsigned r;
    asm("tanh.approx.f16x2 %0, %1;" : "=r"(r) : "r"(u));
    return *reinterpret_cast<__half2*>(&r);
}
__device__ __forceinline__ __half2 sig2(float x0, float x1) {
    const __half2 h05 = __half2half2(__float2half_rn(0.5f));
    __half2 h = __floats2half2_rn(x0, x1);
    h = __hmul2(h, h05);
    __half2 t = htanh2(h);
    return __hfma2(t, h05, h05);
}
// 2 mask bits -> half2 {b0?1:0, b1?1:0}
__device__ __forceinline__ __half2 bits2h2(unsigned nib, int b0, int b1) {
    unsigned r = ((nib >> b0) & 1u ? 0x3C00u : 0u) |
                 ((nib >> b1) & 1u ? 0x3C000000u : 0u);
    return *reinterpret_cast<__half2*>(&r);
}
__device__ __forceinline__ float key2float(unsigned key) {
    return __uint_as_float((key + KOFF) << 13);
}

// ---------------- pack: float mask -> 1 bit/px, and clear hist1 ----------
__global__ void __launch_bounds__(NT) pack_kernel(const float* __restrict__ msk) {
    const int NPX = BATCH * HW;
    int tid = blockIdx.x * NT + threadIdx.x;
    int stride = gridDim.x * NT;
    for (int px = tid; px < NPX; px += stride) {
        bool v = msk[px] > 0.5f;
        unsigned w = __ballot_sync(0xFFFFFFFFu, v);
        if ((threadIdx.x & 31) == 0) g_maskbits[px >> 5] = w;
    }
    unsigned* h1 = &g_hist1[0][0];
    const int NHTOT = BATCH * NHB;
    for (int i = tid; i < NHTOT; i += stride) h1[i] = 0u;
}

// ---------------- dice kernel: one (batch, channel, chunk) per block ------
// 4 iterations of 2-batched load-pairs; fixed reduce tail amortized 2x vs R12.
__global__ void __launch_bounds__(NT, 6) dice_kernel(
    const float4* __restrict__ pred, const float4* __restrict__ gtk)
{
    __shared__ float sred[8][4];
    int blk = blockIdx.x;                 // BATCH*NKC*PBD
    int bc = blk / PBD, chunk = blk % PBD;
    int b = bc / NKC, c = bc % NKC;
    int base4 = chunk * CHUNK4D;

    const float4* pc = pred + ((size_t)b * 6 + 1 + c) * HW4;
    const float4* gc = gtk + ((size_t)b * NKC + c) * HW4;
    const unsigned* __restrict__ bm = g_maskbits + (size_t)b * (HW / 32);

    const __half2 hz = __half2half2(__float2half_rn(0.0f));
    __half2 aint = hz, asii = hz, astt = hz;

    #pragma unroll
    for (int it = 0; it < 4; it++) {
        int idx0 = base4 + threadIdx.x + it * 2 * NT;
        int idx1 = idx0 + NT;
        float4 p0 = pc[idx0], p1 = pc[idx1];
        float4 g0 = gc[idx0], g1 = gc[idx1];
        unsigned n0 = (bm[idx0 >> 3] >> ((idx0 & 7) * 4)) & 0xFu;
        unsigned n1 = (bm[idx1 >> 3] >> ((idx1 & 7) * 4)) & 0xFu;
        {
            __half2 mA = bits2h2(n0, 0, 1), mB = bits2h2(n0, 2, 3);
            __half2 sA = sig2(p0.x, p0.y), sB = sig2(p0.z, p0.w);
            __half2 gA = __floats2half2_rn(g0.x, g0.y), gB = __floats2half2_rn(g0.z, g0.w);
            __half2 smA = __hmul2(sA, mA), smB = __hmul2(sB, mB);
            aint = __hfma2(smA, gA, __hfma2(smB, gB, aint));
            asii = __hfma2(smA, sA, __hfma2(smB, sB, asii));
            astt = __hfma2(gA, mA, __hfma2(gB, mB, astt));
        }
        {
            __half2 mA = bits2h2(n1, 0, 1), mB = bits2h2(n1, 2, 3);
            __half2 sA = sig2(p1.x, p1.y), sB = sig2(p1.z, p1.w);
            __half2 gA = __floats2half2_rn(g1.x, g1.y), gB = __floats2half2_rn(g1.z, g1.w);
            __half2 smA = __hmul2(sA, mA), smB = __hmul2(sB, mB);
            aint = __hfma2(smA, gA, __hfma2(smB, gB, aint));
            asii = __hfma2(smA, sA, __hfma2(smB, sB, asii));
            astt = __hfma2(gA, mA, __hfma2(gB, mB, astt));
        }
    }

    float vals[3];
    vals[0] = __low2float(aint) + __high2float(aint);
    vals[1] = __low2float(asii) + __high2float(asii);
    vals[2] = __low2float(astt) + __high2float(astt);
    #pragma unroll
    for (int j = 0; j < 3; j++) {
        #pragma unroll
        for (int o = 16; o; o >>= 1) vals[j] += __shfl_down_sync(0xFFFFFFFFu, vals[j], o);
    }
    int lane = threadIdx.x & 31, w = threadIdx.x >> 5;
    if (lane == 0) {
        #pragma unroll
        for (int j = 0; j < 3; j++) sred[w][j] = vals[j];
    }
    __syncthreads();
    int t = threadIdx.x;
    if (t < 3) {
        float s = 0.f;
        #pragma unroll
        for (int ww = 0; ww < 8; ww++) s += sred[ww][t];
        int id = b * NKC + c;
        if (t == 0)      atomicAdd(&g_ki[id],  (double)s);
        else if (t == 1) atomicAdd(&g_kii[id], (double)s);
        else             atomicAdd(&g_ktt[id], (double)s);
    }
}

// ---------------- text kernel: pred ch0 x gt_text x mask + histogram ------
__global__ void __launch_bounds__(NT, 6) text_kernel(
    const float4* __restrict__ pred, const float4* __restrict__ gtt,
    const float4* __restrict__ msk)
{
    __shared__ float sred[8][4];
    int b = blockIdx.x / PBT;
    int base4 = (blockIdx.x % PBT) * CHUNK4T;

    const float4* m4 = msk + (size_t)b * HW4;
    const float4* g4 = gtt + (size_t)b * HW4;
    const float4* p4 = pred + (size_t)b * 6 * HW4;   // channel 0 = text
    unsigned* __restrict__ h1 = &g_hist1[b][0];

    float sp = 0.f, sp2 = 0.f, np = 0.f;

    #pragma unroll
    for (int i = 0; i < 4; i++) {
        int idx = base4 + threadIdx.x + i * NT;
        float4 mv = m4[idx];
        float4 gv = g4[idx];
        float4 pv = p4[idx];
        __half2 tA = sig2(pv.x, pv.y);
        __half2 tB = sig2(pv.z, pv.w);
        float ps0 = __low2float(tA), ps1 = __high2float(tA);
        float ps2 = __low2float(tB), ps3 = __high2float(tB);
        #define PROC(COMP, PV)                                                    \
        {                                                                         \
            float m = mv.COMP, g = gv.COMP;                                       \
            float p = PV;                                                         \
            float pm = g * m;                                                     \
            float pp = p * pm;                                                    \
            np += pm; sp += pp; sp2 = fmaf(pp, pp, sp2);                          \
            if (m - g > 0.5f) {       /* negative: m=1 && g=0 */                  \
                unsigned bits = __float_as_uint(p);                               \
                unsigned key = bits >> 13;                                        \
                key = (key > KOFF) ? key - KOFF : 0u;                             \
                if (key >= NHB) key = NHB - 1u;                                   \
                atomicAdd(&h1[key], 1u);                                          \
            }                                                                     \
        }
        PROC(x, ps0) PROC(y, ps1) PROC(z, ps2) PROC(w, ps3)
        #undef PROC
    }

    float vals[3] = {np, sp, sp2};
    #pragma unroll
    for (int j = 0; j < 3; j++) {
        #pragma unroll
        for (int o = 16; o; o >>= 1) vals[j] += __shfl_down_sync(0xFFFFFFFFu, vals[j], o);
    }
    int lane = threadIdx.x & 31, w = threadIdx.x >> 5;
    if (lane == 0) {
        #pragma unroll
        for (int j = 0; j < 3; j++) sred[w][j] = vals[j];
    }
    __syncthreads();
    int t = threadIdx.x;
    if (t < 3) {
        float s = 0.f;
        #pragma unroll
        for (int ww = 0; ww < 8; ww++) s += sred[ww][t];
        if (t == 0)      atomicAdd(&g_npos[b], (unsigned)(s + 0.5f));
        else if (t == 1) atomicAdd(&g_sp[b],  (double)s);
        else             atomicAdd(&g_sp2[b], (double)s);
    }
}

// ---------------- pass2: OHEM select + loss_text; last block does epilogue -
__global__ void __launch_bounds__(1024) pass2_kernel(float* __restrict__ out) {
    int b = blockIdx.x;
    int t = threadIdx.x;
    int lane = t & 31, wid = t >> 5;

    __shared__ unsigned sCntW[32];
    __shared__ double   sWW[32];
    __shared__ unsigned sCntA[32];
    __shared__ double   sWA[32];
    __shared__ unsigned sTotal;
    __shared__ double   sHard;
    __shared__ int      sLast;
    __shared__ double   sd[128];

    // per-thread: 24 contiguous buckets as 6 x uint4 (96B, aligned)
    unsigned cnt[CH];
    int base = t * CH;
    {
        const uint4* hp = reinterpret_cast<const uint4*>(&g_hist1[b][0]) + t * 6;
        #pragma unroll
        for (int j = 0; j < 6; j++) {
            uint4 q = hp[j];
            cnt[4 * j + 0] = q.x; cnt[4 * j + 1] = q.y;
            cnt[4 * j + 2] = q.z; cnt[4 * j + 3] = q.w;
        }
    }
    unsigned s = 0; float wf = 0.f;
    #pragma unroll
    for (int j = 0; j < CH; j++) {
        float v = key2float(base + j);
        s += cnt[j];
        wf = fmaf((float)cnt[j], v * v, wf);
    }
    double w = (double)wf;

    // warp-level inclusive suffix scan
    unsigned sv = s; double wv = w;
    #pragma unroll
    for (int off = 1; off < 32; off <<= 1) {
        unsigned s2 = __shfl_down_sync(0xFFFFFFFFu, sv, off);
        double   w2 = __shfl_down_sync(0xFFFFFFFFu, wv, off);
        if (lane + off < 32) { sv += s2; wv += w2; }
    }
    if (lane == 0) { sCntW[wid] = sv; sWW[wid] = wv; }
    __syncthreads();
    if (wid == 0) {
        unsigned a = sCntW[lane]; double aw = sWW[lane];
        unsigned ai = a; double awi = aw;
        #pragma unroll
        for (int off = 1; off < 32; off <<= 1) {
            unsigned s2 = __shfl_down_sync(0xFFFFFFFFu, ai, off);
            double   w2 = __shfl_down_sync(0xFFFFFFFFu, awi, off);
            if (lane + off < 32) { ai += s2; awi += w2; }
        }
        sCntA[lane] = ai - a;
        sWA[lane]   = awi - aw;
        if (lane == 0) { sTotal = ai; sHard = 0.0; }
    }
    __syncthreads();

    unsigned nneg = sTotal;
    unsigned npos = g_npos[b];
    unsigned k = 3u * npos; if (k > nneg) k = nneg;

    unsigned incl = sv + sCntA[wid];
    unsigned above = incl - s;
    double wincl = wv + sWA[wid];
    double wabove = wincl - w;

    if (k > 0 && above < k && incl >= k) {
        double wacc = wabove;
        unsigned cum = above;
        bool done = false;
        #pragma unroll
        for (int j = CH - 1; j >= 0; j--) {
            if (!done) {
                unsigned c = cnt[j];
                float v = key2float(base + j);
                double v2 = (double)v * (double)v;
                if (cum + c >= k) { sHard = wacc + (double)(k - cum) * v2; done = true; }
                else { cum += c; wacc += (double)c * v2; }
            }
        }
    }
    __syncthreads();

    if (t == 0) {
        double np = (double)npos;
        g_losstext[b] = 1.0 - 2.0 * g_sp[b] / (g_sp2[b] + sHard + np + EPSL);
        g_sp[b] = 0.0; g_sp2[b] = 0.0; g_npos[b] = 0u;
        __threadfence();
        sLast = (atomicAdd(&g_done, 1u) == BATCH - 1);
    }
    __syncthreads();

    if (sLast) {
        double v = 0.0;
        if (t < BATCH * NKC) {
            v = 1.0 - 2.0 * g_ki[t] / (g_kii[t] + g_ktt[t] + EPSL);
            g_ki[t] = 0.0; g_kii[t] = 0.0; g_ktt[t] = 0.0;
        }
        if (t < 128) sd[t] = v;
        __syncthreads();
        #pragma unroll
        for (int o = 64; o; o >>= 1) { if (t < o) sd[t] += sd[t + o]; __syncthreads(); }
        double lk = sd[0] / (double)(BATCH * NKC);
        __syncthreads();
        double lt_in = 0.0;
        if (t < BATCH) { lt_in = g_losstext[t]; g_losstext[t] = 0.0; }
        if (t < 128) sd[t] = lt_in;
        __syncthreads();
        #pragma unroll
        for (int o = 64; o; o >>= 1) { if (t < o) sd[t] += sd[t + o]; __syncthreads(); }
        if (t == 0) {
            double lt = sd[0] / (double)BATCH;
            out[0] = (float)(lk + 0.5 * lt);
            out[1] = (float)lt;
            out[2] = (float)lk;
            g_done = 0u;
        }
    }
}

// ---------------- launch ----------------
extern "C" void kernel_launch(void* const* d_in, const int* in_sizes, int n_in,
                              void* d_out, int out_size) {
    const float4* pred = (const float4*)d_in[0];
    const float4* gtt  = (const float4*)d_in[1];
    const float4* gtk  = (const float4*)d_in[2];
    const float4* msk  = (const float4*)d_in[3];
    float* out = (float*)d_out;

    pack_kernel<<<1024, NT>>>((const float*)d_in[3]);
    dice_kernel<<<BATCH * NKC * PBD, NT>>>(pred, gtk);
    text_kernel<<<BATCH * PBT, NT>>>(pred, gtt, msk);
    pass2_kernel<<<BATCH, 1024>>>(out);
}

// round 15
// speedup vs baseline: 1.3220x; 1.0694x over previous
#include <cuda_runtime.h>
#include <cuda_fp16.h>
#include <cuda_bf16.h>
#include <cstdint>

#define BATCH 16
#define HW 409600
#define HW4 102400
#define NT 256
#define NKC 5
#define EPSL 1e-6

// text kernel tiling
#define PBT 100
#define CHUNK4T 1024
// dice kernel tiling (per-channel blocks)
#define PBD 50
#define CHUNK4D 2048

// f16-derived p has low 13 float bits zero -> key = (bits>>13) - KOFF is lossless
#define KOFF 105472u    // 0x33800000 >> 13  (p = 2^-24, min positive f16)
#define NHB  24576      // keys span [0, 24575] for p in [2^-24, 1)
#define CH   24         // NHB / 1024

// ---------------- scratch (device globals; zero at module load) ------------
// hist1: filled by text, read+RE-ZEROED by pass2 (replay-invariant).
// masknib: fully overwritten by text each run. Scalars reset by consumers.
__device__ unsigned int g_hist1[BATCH][NHB];          // 1.6 MB
__device__ unsigned char g_masknib[BATCH * HW4];      // 1.6 MB, 1 nibble/float4
__device__ double g_sp[BATCH], g_sp2[BATCH], g_losstext[BATCH];
__device__ unsigned int g_npos[BATCH];
__device__ double g_ki[BATCH * NKC], g_kii[BATCH * NKC], g_ktt[BATCH * NKC];
__device__ unsigned int g_done;                       // last-block-done counter

// ---------------- helpers ----------------
__device__ __forceinline__ __half2 htanh2(__half2 v) {
    unsigned u = *reinterpret_cast<unsigned*>(&v);
    unsigned r;
    asm("tanh.approx.f16x2 %0, %1;" : "=r"(r) : "r"(u));
    return *reinterpret_cast<__half2*>(&r);
}
__device__ __forceinline__ __half2 sig2(float x0, float x1) {
    const __half2 h05 = __half2half2(__float2half_rn(0.5f));
    __half2 h = __floats2half2_rn(x0, x1);
    h = __hmul2(h, h05);
    __half2 t = htanh2(h);
    return __hfma2(t, h05, h05);
}
// 2 mask bits -> half2 {b0?1:0, b1?1:0}
__device__ __forceinline__ __half2 bits2h2(unsigned nib, int b0, int b1) {
    unsigned r = ((nib >> b0) & 1u ? 0x3C00u : 0u) |
                 ((nib >> b1) & 1u ? 0x3C000000u : 0u);
    return *reinterpret_cast<__half2*>(&r);
}
__device__ __forceinline__ float key2float(unsigned key) {
    return __uint_as_float((key + KOFF) << 13);
}

// ---------------- text kernel: text sums + histogram + mask nibble pack ---
__global__ void __launch_bounds__(NT, 6) text_kernel(
    const float4* __restrict__ pred, const float4* __restrict__ gtt,
    const float4* __restrict__ msk)
{
    __shared__ float sred[8][4];
    int b = blockIdx.x / PBT;
    int base4 = (blockIdx.x % PBT) * CHUNK4T;

    const float4* m4 = msk + (size_t)b * HW4;
    const float4* g4 = gtt + (size_t)b * HW4;
    const float4* p4 = pred + (size_t)b * 6 * HW4;   // channel 0 = text
    unsigned char* __restrict__ mn = g_masknib + (size_t)b * HW4;
    unsigned* __restrict__ h1 = &g_hist1[b][0];

    float sp = 0.f, sp2 = 0.f, np = 0.f;

    #pragma unroll
    for (int i = 0; i < 4; i++) {
        int idx = base4 + threadIdx.x + i * NT;
        float4 mv = m4[idx];
        float4 gv = __ldcs(&g4[idx]);
        float4 pv = __ldcs(&p4[idx]);
        // pack mask nibble: bit c = component c
        unsigned nib = (mv.x > 0.5f ? 1u : 0u) | (mv.y > 0.5f ? 2u : 0u)
                     | (mv.z > 0.5f ? 4u : 0u) | (mv.w > 0.5f ? 8u : 0u);
        mn[idx] = (unsigned char)nib;

        __half2 tA = sig2(pv.x, pv.y);
        __half2 tB = sig2(pv.z, pv.w);
        float ps0 = __low2float(tA), ps1 = __high2float(tA);
        float ps2 = __low2float(tB), ps3 = __high2float(tB);
        #define PROC(COMP, PV)                                                    \
        {                                                                         \
            float m = mv.COMP, g = gv.COMP;                                       \
            float p = PV;                                                         \
            float pm = g * m;                                                     \
            float pp = p * pm;                                                    \
            np += pm; sp += pp; sp2 = fmaf(pp, pp, sp2);                          \
            if (m - g > 0.5f) {       /* negative: m=1 && g=0 */                  \
                unsigned bits = __float_as_uint(p);                               \
                unsigned key = bits >> 13;                                        \
                key = (key > KOFF) ? key - KOFF : 0u;                             \
                if (key >= NHB) key = NHB - 1u;                                   \
                atomicAdd(&h1[key], 1u);                                          \
            }                                                                     \
        }
        PROC(x, ps0) PROC(y, ps1) PROC(z, ps2) PROC(w, ps3)
        #undef PROC
    }

    float vals[3] = {np, sp, sp2};
    #pragma unroll
    for (int j = 0; j < 3; j++) {
        #pragma unroll
        for (int o = 16; o; o >>= 1) vals[j] += __shfl_down_sync(0xFFFFFFFFu, vals[j], o);
    }
    int lane = threadIdx.x & 31, w = threadIdx.x >> 5;
    if (lane == 0) {
        #pragma unroll
        for (int j = 0; j < 3; j++) sred[w][j] = vals[j];
    }
    __syncthreads();
    int t = threadIdx.x;
    if (t < 3) {
        float s = 0.f;
        #pragma unroll
        for (int ww = 0; ww < 8; ww++) s += sred[ww][t];
        if (t == 0)      atomicAdd(&g_npos[b], (unsigned)(s + 0.5f));
        else if (t == 1) atomicAdd(&g_sp[b],  (double)s);
        else             atomicAdd(&g_sp2[b], (double)s);
    }
}

// ---------------- dice kernel: one (batch, channel, chunk) per block ------
__global__ void __launch_bounds__(NT, 6) dice_kernel(
    const float4* __restrict__ pred, const float4* __restrict__ gtk)
{
    __shared__ float sred[8][4];
    int blk = blockIdx.x;                 // BATCH*NKC*PBD
    int bc = blk / PBD, chunk = blk % PBD;
    int b = bc / NKC, c = bc % NKC;
    int base4 = chunk * CHUNK4D;

    const float4* pc = pred + ((size_t)b * 6 + 1 + c) * HW4;
    const float4* gc = gtk + ((size_t)b * NKC + c) * HW4;
    const unsigned char* __restrict__ mn = g_masknib + (size_t)b * HW4;

    const __half2 hz = __half2half2(__float2half_rn(0.0f));
    __half2 aint = hz, asii = hz, astt = hz;

    #pragma unroll
    for (int it = 0; it < 4; it++) {
        int idx0 = base4 + threadIdx.x + it * 2 * NT;
        int idx1 = idx0 + NT;
        float4 p0 = __ldcs(&pc[idx0]), p1 = __ldcs(&pc[idx1]);
        float4 g0 = __ldcs(&gc[idx0]), g1 = __ldcs(&gc[idx1]);
        unsigned n0 = mn[idx0];
        unsigned n1 = mn[idx1];
        {
            __half2 mA = bits2h2(n0, 0, 1), mB = bits2h2(n0, 2, 3);
            __half2 sA = sig2(p0.x, p0.y), sB = sig2(p0.z, p0.w);
            __half2 gA = __floats2half2_rn(g0.x, g0.y), gB = __floats2half2_rn(g0.z, g0.w);
            __half2 smA = __hmul2(sA, mA), smB = __hmul2(sB, mB);
            aint = __hfma2(smA, gA, __hfma2(smB, gB, aint));
            asii = __hfma2(smA, sA, __hfma2(smB, sB, asii));
            astt = __hfma2(gA, mA, __hfma2(gB, mB, astt));
        }
        {
            __half2 mA = bits2h2(n1, 0, 1), mB = bits2h2(n1, 2, 3);
            __half2 sA = sig2(p1.x, p1.y), sB = sig2(p1.z, p1.w);
            __half2 gA = __floats2half2_rn(g1.x, g1.y), gB = __floats2half2_rn(g1.z, g1.w);
            __half2 smA = __hmul2(sA, mA), smB = __hmul2(sB, mB);
            aint = __hfma2(smA, gA, __hfma2(smB, gB, aint));
            asii = __hfma2(smA, sA, __hfma2(smB, sB, asii));
            astt = __hfma2(gA, mA, __hfma2(gB, mB, astt));
        }
    }

    float vals[3];
    vals[0] = __low2float(aint) + __high2float(aint);
    vals[1] = __low2float(asii) + __high2float(asii);
    vals[2] = __low2float(astt) + __high2float(astt);
    #pragma unroll
    for (int j = 0; j < 3; j++) {
        #pragma unroll
        for (int o = 16; o; o >>= 1) vals[j] += __shfl_down_sync(0xFFFFFFFFu, vals[j], o);
    }
    int lane = threadIdx.x & 31, w = threadIdx.x >> 5;
    if (lane == 0) {
        #pragma unroll
        for (int j = 0; j < 3; j++) sred[w][j] = vals[j];
    }
    __syncthreads();
    int t = threadIdx.x;
    if (t < 3) {
        float s = 0.f;
        #pragma unroll
        for (int ww = 0; ww < 8; ww++) s += sred[ww][t];
        int id = b * NKC + c;
        if (t == 0)      atomicAdd(&g_ki[id],  (double)s);
        else if (t == 1) atomicAdd(&g_kii[id], (double)s);
        else             atomicAdd(&g_ktt[id], (double)s);
    }
}

// ---------------- pass2: OHEM select + loss_text + hist clear + epilogue --
__global__ void __launch_bounds__(1024) pass2_kernel(float* __restrict__ out) {
    int b = blockIdx.x;
    int t = threadIdx.x;
    int lane = t & 31, wid = t >> 5;

    __shared__ unsigned sCntW[32];
    __shared__ double   sWW[32];
    __shared__ unsigned sCntA[32];
    __shared__ double   sWA[32];
    __shared__ unsigned sTotal;
    __shared__ double   sHard;
    __shared__ int      sLast;
    __shared__ double   sd[128];

    // per-thread: 24 contiguous buckets as 6 x uint4; clear after reading
    unsigned cnt[CH];
    {
        uint4* hp = reinterpret_cast<uint4*>(&g_hist1[b][0]) + t * 6;
        const uint4 z4 = make_uint4(0u, 0u, 0u, 0u);
        #pragma unroll
        for (int j = 0; j < 6; j++) {
            uint4 q = hp[j];
            cnt[4 * j + 0] = q.x; cnt[4 * j + 1] = q.y;
            cnt[4 * j + 2] = q.z; cnt[4 * j + 3] = q.w;
            hp[j] = z4;   // restore zero for next replay
        }
    }
    int base = t * CH;
    unsigned s = 0; float wf = 0.f;
    #pragma unroll
    for (int j = 0; j < CH; j++) {
        float v = key2float(base + j);
        s += cnt[j];
        wf = fmaf((float)cnt[j], v * v, wf);
    }
    double w = (double)wf;

    // warp-level inclusive suffix scan
    unsigned sv = s; double wv = w;
    #pragma unroll
    for (int off = 1; off < 32; off <<= 1) {
        unsigned s2 = __shfl_down_sync(0xFFFFFFFFu, sv, off);
        double   w2 = __shfl_down_sync(0xFFFFFFFFu, wv, off);
        if (lane + off < 32) { sv += s2; wv += w2; }
    }
    if (lane == 0) { sCntW[wid] = sv; sWW[wid] = wv; }
    __syncthreads();
    if (wid == 0) {
        unsigned a = sCntW[lane]; double aw = sWW[lane];
        unsigned ai = a; double awi = aw;
        #pragma unroll
        for (int off = 1; off < 32; off <<= 1) {
            unsigned s2 = __shfl_down_sync(0xFFFFFFFFu, ai, off);
            double   w2 = __shfl_down_sync(0xFFFFFFFFu, awi, off);
            if (lane + off < 32) { ai += s2; awi += w2; }
        }
        sCntA[lane] = ai - a;
        sWA[lane]   = awi - aw;
        if (lane == 0) { sTotal = ai; sHard = 0.0; }
    }
    __syncthreads();

    unsigned nneg = sTotal;
    unsigned npos = g_npos[b];
    unsigned k = 3u * npos; if (k > nneg) k = nneg;

    unsigned incl = sv + sCntA[wid];
    unsigned above = incl - s;
    double wincl = wv + sWA[wid];
    double wabove = wincl - w;

    if (k > 0 && above < k && incl >= k) {
        double wacc = wabove;
        unsigned cum = above;
        bool done = false;
        #pragma unroll
        for (int j = CH - 1; j >= 0; j--) {
            if (!done) {
                unsigned c = cnt[j];
                float v = key2float(base + j);
                double v2 = (double)v * (double)v;
                if (cum + c >= k) { sHard = wacc + (double)(k - cum) * v2; done = true; }
                else { cum += c; wacc += (double)c * v2; }
            }
        }
    }
    __syncthreads();

    if (t == 0) {
        double np = (double)npos;
        g_losstext[b] = 1.0 - 2.0 * g_sp[b] / (g_sp2[b] + sHard + np + EPSL);
        g_sp[b] = 0.0; g_sp2[b] = 0.0; g_npos[b] = 0u;
        __threadfence();
        sLast = (atomicAdd(&g_done, 1u) == BATCH - 1);
    }
    __syncthreads();

    if (sLast) {
        double v = 0.0;
        if (t < BATCH * NKC) {
            v = 1.0 - 2.0 * g_ki[t] / (g_kii[t] + g_ktt[t] + EPSL);
            g_ki[t] = 0.0; g_kii[t] = 0.0; g_ktt[t] = 0.0;
        }
        if (t < 128) sd[t] = v;
        __syncthreads();
        #pragma unroll
        for (int o = 64; o; o >>= 1) { if (t < o) sd[t] += sd[t + o]; __syncthreads(); }
        double lk = sd[0] / (double)(BATCH * NKC);
        __syncthreads();
        double lt_in = 0.0;
        if (t < BATCH) { lt_in = g_losstext[t]; g_losstext[t] = 0.0; }
        if (t < 128) sd[t] = lt_in;
        __syncthreads();
        #pragma unroll
        for (int o = 64; o; o >>= 1) { if (t < o) sd[t] += sd[t + o]; __syncthreads(); }
        if (t == 0) {
            double lt = sd[0] / (double)BATCH;
            out[0] = (float)(lk + 0.5 * lt);
            out[1] = (float)lt;
            out[2] = (float)lk;
            g_done = 0u;
        }
    }
}

// ---------------- launch ----------------
extern "C" void kernel_launch(void* const* d_in, const int* in_sizes, int n_in,
                              void* d_out, int out_size) {
    const float4* pred = (const float4*)d_in[0];
    const float4* gtt  = (const float4*)d_in[1];
    const float4* gtk  = (const float4*)d_in[2];
    const float4* msk  = (const float4*)d_in[3];
    float* out = (float*)d_out;

    text_kernel<<<BATCH * PBT, NT>>>(pred, gtt, msk);
    dice_kernel<<<BATCH * NKC * PBD, NT>>>(pred, gtk);
    pass2_kernel<<<BATCH, 1024>>>(out);
}

// round 16
// speedup vs baseline: 2.6781x; 2.0258x over previous
#include <cuda_runtime.h>
#include <cuda_fp16.h>
#include <cuda_bf16.h>
#include <cstdint>

#define BATCH 16
#define HW 409600
#define HW4 102400
#define NT 256
#define NKC 5
#define EPSL 1e-6

// text kernel: blocks per batch (grid-stride within batch)
#define BPB 36
// dice kernel tiling (per-channel blocks)
#define PBD 50
#define CHUNK4D 2048

// f16-derived p has low 13 float bits zero; full key = (bits>>13)-KOFF.
// Coarse key = fullkey>>3 -> 3072 buckets (12KB smem histogram per block).
#define KOFF 105472u    // 0x33800000 >> 13  (p = 2^-24, min positive f16)
#define SHIFT 3
#define NHB  3072       // coarse buckets
#define NHBF (NHB << SHIFT)   // 24576 full keys
#define CH   3          // buckets per pass2 thread (3072/1024)

// ---------------- scratch (device globals; zero at module load) ------------
// hist1: filled by text (smem-privatized + merge), read+RE-ZEROED by pass2.
// masknib: fully overwritten by text each run. Scalars reset by consumers.
__device__ unsigned int g_hist1[BATCH][NHB];          // 192 KB
__device__ unsigned char g_masknib[BATCH * HW4];      // 1.6 MB, 1 nibble/float4
__device__ double g_sp[BATCH], g_sp2[BATCH], g_losstext[BATCH];
__device__ unsigned int g_npos[BATCH];
__device__ double g_ki[BATCH * NKC], g_kii[BATCH * NKC], g_ktt[BATCH * NKC];
__device__ unsigned int g_done;                       // last-block-done counter

// ---------------- helpers ----------------
__device__ __forceinline__ __half2 htanh2(__half2 v) {
    unsigned u = *reinterpret_cast<unsigned*>(&v);
    unsigned r;
    asm("tanh.approx.f16x2 %0, %1;" : "=r"(r) : "r"(u));
    return *reinterpret_cast<__half2*>(&r);
}
__device__ __forceinline__ __half2 sig2(float x0, float x1) {
    const __half2 h05 = __half2half2(__float2half_rn(0.5f));
    __half2 h = __floats2half2_rn(x0, x1);
    h = __hmul2(h, h05);
    __half2 t = htanh2(h);
    return __hfma2(t, h05, h05);
}
// 2 mask bits -> half2 {b0?1:0, b1?1:0}
__device__ __forceinline__ __half2 bits2h2(unsigned nib, int b0, int b1) {
    unsigned r = ((nib >> b0) & 1u ? 0x3C00u : 0u) |
                 ((nib >> b1) & 1u ? 0x3C000000u : 0u);
    return *reinterpret_cast<__half2*>(&r);
}
// coarse bucket midpoint value
__device__ __forceinline__ float bucket2float(unsigned coarse) {
    return __uint_as_float(((coarse << SHIFT) + 4u + KOFF) << 13);
}

// ---------------- text kernel: sums + smem histogram + mask nibble pack ---
__global__ void __launch_bounds__(NT) text_kernel(
    const float4* __restrict__ pred, const float4* __restrict__ gtt,
    const float4* __restrict__ msk)
{
    __shared__ unsigned shist[NHB];   // 12 KB private histogram
    __shared__ float sred[8][4];
    int b = blockIdx.x / BPB;
    int sub = blockIdx.x % BPB;

    for (int i = threadIdx.x; i < NHB; i += NT) shist[i] = 0u;
    __syncthreads();

    const float4* m4 = msk + (size_t)b * HW4;
    const float4* g4 = gtt + (size_t)b * HW4;
    const float4* p4 = pred + (size_t)b * 6 * HW4;   // channel 0 = text
    unsigned char* __restrict__ mn = g_masknib + (size_t)b * HW4;

    float sp = 0.f, sp2 = 0.f, np = 0.f;

    for (int idx = sub * NT + threadIdx.x; idx < HW4; idx += BPB * NT) {
        float4 mv = m4[idx];
        float4 gv = __ldcs(&g4[idx]);
        float4 pv = __ldcs(&p4[idx]);
        unsigned nib = (mv.x > 0.5f ? 1u : 0u) | (mv.y > 0.5f ? 2u : 0u)
                     | (mv.z > 0.5f ? 4u : 0u) | (mv.w > 0.5f ? 8u : 0u);
        mn[idx] = (unsigned char)nib;

        __half2 tA = sig2(pv.x, pv.y);
        __half2 tB = sig2(pv.z, pv.w);
        float ps0 = __low2float(tA), ps1 = __high2float(tA);
        float ps2 = __low2float(tB), ps3 = __high2float(tB);
        #define PROC(COMP, PV)                                                    \
        {                                                                         \
            float m = mv.COMP, g = gv.COMP;                                       \
            float p = PV;                                                         \
            float pm = g * m;                                                     \
            float pp = p * pm;                                                    \
            np += pm; sp += pp; sp2 = fmaf(pp, pp, sp2);                          \
            if (m - g > 0.5f) {       /* negative: m=1 && g=0 */                  \
                unsigned bits = __float_as_uint(p);                               \
                unsigned key = bits >> 13;                                        \
                key = (key > KOFF) ? key - KOFF : 0u;                             \
                if (key >= NHBF) key = NHBF - 1u;                                 \
                atomicAdd(&shist[key >> SHIFT], 1u);                              \
            }                                                                     \
        }
        PROC(x, ps0) PROC(y, ps1) PROC(z, ps2) PROC(w, ps3)
        #undef PROC
    }
    __syncthreads();

    // merge non-zero buckets into the per-batch global histogram
    unsigned* __restrict__ h1 = &g_hist1[b][0];
    for (int i = threadIdx.x; i < NHB; i += NT) {
        unsigned c = shist[i];
        if (c) atomicAdd(&h1[i], c);
    }

    float vals[3] = {np, sp, sp2};
    #pragma unroll
    for (int j = 0; j < 3; j++) {
        #pragma unroll
        for (int o = 16; o; o >>= 1) vals[j] += __shfl_down_sync(0xFFFFFFFFu, vals[j], o);
    }
    int lane = threadIdx.x & 31, w = threadIdx.x >> 5;
    if (lane == 0) {
        #pragma unroll
        for (int j = 0; j < 3; j++) sred[w][j] = vals[j];
    }
    __syncthreads();
    int t = threadIdx.x;
    if (t < 3) {
        float s = 0.f;
        #pragma unroll
        for (int ww = 0; ww < 8; ww++) s += sred[ww][t];
        if (t == 0)      atomicAdd(&g_npos[b], (unsigned)(s + 0.5f));
        else if (t == 1) atomicAdd(&g_sp[b],  (double)s);
        else             atomicAdd(&g_sp2[b], (double)s);
    }
}

// ---------------- dice kernel: one (batch, channel, chunk) per block ------
__global__ void __launch_bounds__(NT, 6) dice_kernel(
    const float4* __restrict__ pred, const float4* __restrict__ gtk)
{
    __shared__ float sred[8][4];
    int blk = blockIdx.x;                 // BATCH*NKC*PBD
    int bc = blk / PBD, chunk = blk % PBD;
    int b = bc / NKC, c = bc % NKC;
    int base4 = chunk * CHUNK4D;

    const float4* pc = pred + ((size_t)b * 6 + 1 + c) * HW4;
    const float4* gc = gtk + ((size_t)b * NKC + c) * HW4;
    const unsigned char* __restrict__ mn = g_masknib + (size_t)b * HW4;

    const __half2 hz = __half2half2(__float2half_rn(0.0f));
    __half2 aint = hz, asii = hz, astt = hz;

    #pragma unroll
    for (int it = 0; it < 4; it++) {
        int idx0 = base4 + threadIdx.x + it * 2 * NT;
        int idx1 = idx0 + NT;
        float4 p0 = __ldcs(&pc[idx0]), p1 = __ldcs(&pc[idx1]);
        float4 g0 = __ldcs(&gc[idx0]), g1 = __ldcs(&gc[idx1]);
        unsigned n0 = mn[idx0];
        unsigned n1 = mn[idx1];
        {
            __half2 mA = bits2h2(n0, 0, 1), mB = bits2h2(n0, 2, 3);
            __half2 sA = sig2(p0.x, p0.y), sB = sig2(p0.z, p0.w);
            __half2 gA = __floats2half2_rn(g0.x, g0.y), gB = __floats2half2_rn(g0.z, g0.w);
            __half2 smA = __hmul2(sA, mA), smB = __hmul2(sB, mB);
            aint = __hfma2(smA, gA, __hfma2(smB, gB, aint));
            asii = __hfma2(smA, sA, __hfma2(smB, sB, asii));
            astt = __hfma2(gA, mA, __hfma2(gB, mB, astt));
        }
        {
            __half2 mA = bits2h2(n1, 0, 1), mB = bits2h2(n1, 2, 3);
            __half2 sA = sig2(p1.x, p1.y), sB = sig2(p1.z, p1.w);
            __half2 gA = __floats2half2_rn(g1.x, g1.y), gB = __floats2half2_rn(g1.z, g1.w);
            __half2 smA = __hmul2(sA, mA), smB = __hmul2(sB, mB);
            aint = __hfma2(smA, gA, __hfma2(smB, gB, aint));
            asii = __hfma2(smA, sA, __hfma2(smB, sB, asii));
            astt = __hfma2(gA, mA, __hfma2(gB, mB, astt));
        }
    }

    float vals[3];
    vals[0] = __low2float(aint) + __high2float(aint);
    vals[1] = __low2float(asii) + __high2float(asii);
    vals[2] = __low2float(astt) + __high2float(astt);
    #pragma unroll
    for (int j = 0; j < 3; j++) {
        #pragma unroll
        for (int o = 16; o; o >>= 1) vals[j] += __shfl_down_sync(0xFFFFFFFFu, vals[j], o);
    }
    int lane = threadIdx.x & 31, w = threadIdx.x >> 5;
    if (lane == 0) {
        #pragma unroll
        for (int j = 0; j < 3; j++) sred[w][j] = vals[j];
    }
    __syncthreads();
    int t = threadIdx.x;
    if (t < 3) {
        float s = 0.f;
        #pragma unroll
        for (int ww = 0; ww < 8; ww++) s += sred[ww][t];
        int id = b * NKC + c;
        if (t == 0)      atomicAdd(&g_ki[id],  (double)s);
        else if (t == 1) atomicAdd(&g_kii[id], (double)s);
        else             atomicAdd(&g_ktt[id], (double)s);
    }
}

// ---------------- pass2: OHEM select + loss_text + hist clear + epilogue --
__global__ void __launch_bounds__(1024) pass2_kernel(float* __restrict__ out) {
    int b = blockIdx.x;
    int t = threadIdx.x;
    int lane = t & 31, wid = t >> 5;

    __shared__ unsigned sCntW[32];
    __shared__ double   sWW[32];
    __shared__ unsigned sCntA[32];
    __shared__ double   sWA[32];
    __shared__ unsigned sTotal;
    __shared__ double   sHard;
    __shared__ int      sLast;
    __shared__ double   sd[128];

    // per-thread: 3 contiguous coarse buckets; clear after reading
    unsigned cnt[CH];
    int base = t * CH;
    #pragma unroll
    for (int j = 0; j < CH; j++) {
        cnt[j] = g_hist1[b][base + j];
        g_hist1[b][base + j] = 0u;   // restore zero for next replay
    }
    unsigned s = 0; float wf = 0.f;
    #pragma unroll
    for (int j = 0; j < CH; j++) {
        float v = bucket2float(base + j);
        s += cnt[j];
        wf = fmaf((float)cnt[j], v * v, wf);
    }
    double w = (double)wf;

    // warp-level inclusive suffix scan
    unsigned sv = s; double wv = w;
    #pragma unroll
    for (int off = 1; off < 32; off <<= 1) {
        unsigned s2 = __shfl_down_sync(0xFFFFFFFFu, sv, off);
        double   w2 = __shfl_down_sync(0xFFFFFFFFu, wv, off);
        if (lane + off < 32) { sv += s2; wv += w2; }
    }
    if (lane == 0) { sCntW[wid] = sv; sWW[wid] = wv; }
    __syncthreads();
    if (wid == 0) {
        unsigned a = sCntW[lane]; double aw = sWW[lane];
        unsigned ai = a; double awi = aw;
        #pragma unroll
        for (int off = 1; off < 32; off <<= 1) {
            unsigned s2 = __shfl_down_sync(0xFFFFFFFFu, ai, off);
            double   w2 = __shfl_down_sync(0xFFFFFFFFu, awi, off);
            if (lane + off < 32) { ai += s2; awi += w2; }
        }
        sCntA[lane] = ai - a;
        sWA[lane]   = awi - aw;
        if (lane == 0) { sTotal = ai; sHard = 0.0; }
    }
    __syncthreads();

    unsigned nneg = sTotal;
    unsigned npos = g_npos[b];
    unsigned k = 3u * npos; if (k > nneg) k = nneg;

    unsigned incl = sv + sCntA[wid];
    unsigned above = incl - s;
    double wincl = wv + sWA[wid];
    double wabove = wincl - w;

    if (k > 0 && above < k && incl >= k) {
        double wacc = wabove;
        unsigned cum = above;
        bool done = false;
        #pragma unroll
        for (int j = CH - 1; j >= 0; j--) {
            if (!done) {
                unsigned c = cnt[j];
                float v = bucket2float(base + j);
                double v2 = (double)v * (double)v;
                if (cum + c >= k) { sHard = wacc + (double)(k - cum) * v2; done = true; }
                else { cum += c; wacc += (double)c * v2; }
            }
        }
    }
    __syncthreads();

    if (t == 0) {
        double np = (double)npos;
        g_losstext[b] = 1.0 - 2.0 * g_sp[b] / (g_sp2[b] + sHard + np + EPSL);
        g_sp[b] = 0.0; g_sp2[b] = 0.0; g_npos[b] = 0u;
        __threadfence();
        sLast = (atomicAdd(&g_done, 1u) == BATCH - 1);
    }
    __syncthreads();

    if (sLast) {
        double v = 0.0;
        if (t < BATCH * NKC) {
            v = 1.0 - 2.0 * g_ki[t] / (g_kii[t] + g_ktt[t] + EPSL);
            g_ki[t] = 0.0; g_kii[t] = 0.0; g_ktt[t] = 0.0;
        }
        if (t < 128) sd[t] = v;
        __syncthreads();
        #pragma unroll
        for (int o = 64; o; o >>= 1) { if (t < o) sd[t] += sd[t + o]; __syncthreads(); }
        double lk = sd[0] / (double)(BATCH * NKC);
        __syncthreads();
        double lt_in = 0.0;
        if (t < BATCH) { lt_in = g_losstext[t]; g_losstext[t] = 0.0; }
        if (t < 128) sd[t] = lt_in;
        __syncthreads();
        #pragma unroll
        for (int o = 64; o; o >>= 1) { if (t < o) sd[t] += sd[t + o]; __syncthreads(); }
        if (t == 0) {
            double lt = sd[0] / (double)BATCH;
            out[0] = (float)(lk + 0.5 * lt);
            out[1] = (float)lt;
            out[2] = (float)lk;
            g_done = 0u;
        }
    }
}

// ---------------- launch ----------------
extern "C" void kernel_launch(void* const* d_in, const int* in_sizes, int n_in,
                              void* d_out, int out_size) {
    const float4* pred = (const float4*)d_in[0];
    const float4* gtt  = (const float4*)d_in[1];
    const float4* gtk  = (const float4*)d_in[2];
    const float4* msk  = (const float4*)d_in[3];
    float* out = (float*)d_out;

    text_kernel<<<BATCH * BPB, NT>>>(pred, gtt, msk);
    dice_kernel<<<BATCH * NKC * PBD, NT>>>(pred, gtk);
    pass2_kernel<<<BATCH, 1024>>>(out);
}

// round 17
// speedup vs baseline: 2.9838x; 1.1141x over previous
#include <cuda_runtime.h>
#include <cuda_fp16.h>
#include <cuda_bf16.h>
#include <cstdint>

#define BATCH 16
#define HW 409600
#define HW4 102400
#define NT 256
#define NKC 5
#define EPSL 1e-6

// text kernel: blocks per batch (grid-stride within batch)
#define BPB 72
// dice kernel tiling (per-channel blocks)
#define PBD 50
#define CHUNK4D 2048
#define DICE_BLKS (BATCH * NKC * PBD)
#define TOTAL_BLKS (DICE_BLKS + BATCH)

// f16-derived p has low 13 float bits zero; full key = (bits>>13)-KOFF.
// Coarse key = fullkey>>3 -> 3072 buckets (12KB smem histogram per block).
#define KOFF 105472u    // 0x33800000 >> 13  (p = 2^-24, min positive f16)
#define SHIFT 3
#define NHB  3072       // coarse buckets
#define NHBF (NHB << SHIFT)   // 24576 full keys
#define CH2  12         // buckets per pass2-role thread (3072/256)

// ---------------- scratch (device globals; zero at module load) ------------
// hist1: filled by text, read+RE-ZEROED by pass2-role blocks.
// masknib: fully overwritten by text each run. Scalars reset by consumers.
__device__ unsigned int g_hist1[BATCH][NHB];          // 192 KB
__device__ unsigned char g_masknib[BATCH * HW4];      // 1.6 MB
__device__ double g_sp[BATCH], g_sp2[BATCH], g_losstext[BATCH];
__device__ unsigned int g_npos[BATCH];
__device__ double g_ki[BATCH * NKC], g_kii[BATCH * NKC], g_ktt[BATCH * NKC];
__device__ unsigned int g_done;                       // last-block-done counter

// ---------------- helpers ----------------
__device__ __forceinline__ __half2 htanh2(__half2 v) {
    unsigned u = *reinterpret_cast<unsigned*>(&v);
    unsigned r;
    asm("tanh.approx.f16x2 %0, %1;" : "=r"(r) : "r"(u));
    return *reinterpret_cast<__half2*>(&r);
}
__device__ __forceinline__ __half2 sig2(float x0, float x1) {
    const __half2 h05 = __half2half2(__float2half_rn(0.5f));
    __half2 h = __floats2half2_rn(x0, x1);
    h = __hmul2(h, h05);
    __half2 t = htanh2(h);
    return __hfma2(t, h05, h05);
}
__device__ __forceinline__ __half2 bits2h2(unsigned nib, int b0, int b1) {
    unsigned r = ((nib >> b0) & 1u ? 0x3C00u : 0u) |
                 ((nib >> b1) & 1u ? 0x3C000000u : 0u);
    return *reinterpret_cast<__half2*>(&r);
}
// coarse bucket midpoint value
__device__ __forceinline__ float bucket2float(unsigned coarse) {
    return __uint_as_float(((coarse << SHIFT) + 4u + KOFF) << 13);
}

// ---------------- text kernel: sums + smem histogram + mask nibble pack ---
__global__ void __launch_bounds__(NT) text_kernel(
    const float4* __restrict__ pred, const float4* __restrict__ gtt,
    const float4* __restrict__ msk)
{
    __shared__ unsigned shist[NHB];   // 12 KB private histogram
    __shared__ float sred[8][4];
    int b = blockIdx.x / BPB;
    int sub = blockIdx.x % BPB;

    for (int i = threadIdx.x; i < NHB; i += NT) shist[i] = 0u;
    __syncthreads();

    const float4* m4 = msk + (size_t)b * HW4;
    const float4* g4 = gtt + (size_t)b * HW4;
    const float4* p4 = pred + (size_t)b * 6 * HW4;   // channel 0 = text
    unsigned char* __restrict__ mn = g_masknib + (size_t)b * HW4;

    float sp = 0.f, sp2 = 0.f, np = 0.f;

    for (int idx = sub * NT + threadIdx.x; idx < HW4; idx += BPB * NT) {
        float4 mv = m4[idx];
        float4 gv = __ldcs(&g4[idx]);
        float4 pv = __ldcs(&p4[idx]);
        unsigned nib = (mv.x > 0.5f ? 1u : 0u) | (mv.y > 0.5f ? 2u : 0u)
                     | (mv.z > 0.5f ? 4u : 0u) | (mv.w > 0.5f ? 8u : 0u);
        mn[idx] = (unsigned char)nib;

        __half2 tA = sig2(pv.x, pv.y);
        __half2 tB = sig2(pv.z, pv.w);
        float ps0 = __low2float(tA), ps1 = __high2float(tA);
        float ps2 = __low2float(tB), ps3 = __high2float(tB);
        #define PROC(COMP, PV)                                                    \
        {                                                                         \
            float m = mv.COMP, g = gv.COMP;                                       \
            float p = PV;                                                         \
            float pm = g * m;                                                     \
            float pp = p * pm;                                                    \
            np += pm; sp += pp; sp2 = fmaf(pp, pp, sp2);                          \
            if (m - g > 0.5f) {       /* negative: m=1 && g=0 */                  \
                unsigned bits = __float_as_uint(p);                               \
                unsigned key = bits >> 13;                                        \
                key = (key > KOFF) ? key - KOFF : 0u;                             \
                if (key >= NHBF) key = NHBF - 1u;                                 \
                atomicAdd(&shist[key >> SHIFT], 1u);                              \
            }                                                                     \
        }
        PROC(x, ps0) PROC(y, ps1) PROC(z, ps2) PROC(w, ps3)
        #undef PROC
    }
    __syncthreads();

    unsigned* __restrict__ h1 = &g_hist1[b][0];
    for (int i = threadIdx.x; i < NHB; i += NT) {
        unsigned c = shist[i];
        if (c) atomicAdd(&h1[i], c);
    }

    float vals[3] = {np, sp, sp2};
    #pragma unroll
    for (int j = 0; j < 3; j++) {
        #pragma unroll
        for (int o = 16; o; o >>= 1) vals[j] += __shfl_down_sync(0xFFFFFFFFu, vals[j], o);
    }
    int lane = threadIdx.x & 31, w = threadIdx.x >> 5;
    if (lane == 0) {
        #pragma unroll
        for (int j = 0; j < 3; j++) sred[w][j] = vals[j];
    }
    __syncthreads();
    int t = threadIdx.x;
    if (t < 3) {
        float s = 0.f;
        #pragma unroll
        for (int ww = 0; ww < 8; ww++) s += sred[ww][t];
        if (t == 0)      atomicAdd(&g_npos[b], (unsigned)(s + 0.5f));
        else if (t == 1) atomicAdd(&g_sp[b],  (double)s);
        else             atomicAdd(&g_sp2[b], (double)s);
    }
}

// ---------------- dice kernel with fused pass2 tail + epilogue ------------
// Blocks [0, DICE_BLKS): dice channel partial sums.
// Blocks [DICE_BLKS, TOTAL_BLKS): pass2 select for batch (blk - DICE_BLKS).
// Last finishing block (g_done counter) computes the 3 outputs.
__global__ void __launch_bounds__(NT, 6) dice_kernel(
    const float4* __restrict__ pred, const float4* __restrict__ gtk,
    float* __restrict__ out)
{
    __shared__ float sred[8][4];
    __shared__ unsigned sCntW[8];
    __shared__ double   sWW[8];
    __shared__ unsigned sCntA[8];
    __shared__ double   sWA[8];
    __shared__ unsigned sTotal;
    __shared__ double   sHard;
    __shared__ int      sLast;
    __shared__ double   sd[128];

    int blk = blockIdx.x;
    int t = threadIdx.x;
    int lane = t & 31, wid = t >> 5;

    if (blk < DICE_BLKS) {
        // ================= dice role =================
        int bc = blk / PBD, chunk = blk % PBD;
        int b = bc / NKC, c = bc % NKC;
        int base4 = chunk * CHUNK4D;

        const float4* pc = pred + ((size_t)b * 6 + 1 + c) * HW4;
        const float4* gc = gtk + ((size_t)b * NKC + c) * HW4;
        const unsigned char* __restrict__ mn = g_masknib + (size_t)b * HW4;

        const __half2 hz = __half2half2(__float2half_rn(0.0f));
        __half2 aint = hz, asii = hz, astt = hz;

        #pragma unroll
        for (int it = 0; it < 4; it++) {
            int idx0 = base4 + t + it * 2 * NT;
            int idx1 = idx0 + NT;
            float4 p0 = __ldcs(&pc[idx0]), p1 = __ldcs(&pc[idx1]);
            float4 g0 = __ldcs(&gc[idx0]), g1 = __ldcs(&gc[idx1]);
            unsigned n0 = mn[idx0];
            unsigned n1 = mn[idx1];
            {
                __half2 mA = bits2h2(n0, 0, 1), mB = bits2h2(n0, 2, 3);
                __half2 sA = sig2(p0.x, p0.y), sB = sig2(p0.z, p0.w);
                __half2 gA = __floats2half2_rn(g0.x, g0.y), gB = __floats2half2_rn(g0.z, g0.w);
                __half2 smA = __hmul2(sA, mA), smB = __hmul2(sB, mB);
                aint = __hfma2(smA, gA, __hfma2(smB, gB, aint));
                asii = __hfma2(smA, sA, __hfma2(smB, sB, asii));
                astt = __hfma2(gA, mA, __hfma2(gB, mB, astt));
            }
            {
                __half2 mA = bits2h2(n1, 0, 1), mB = bits2h2(n1, 2, 3);
                __half2 sA = sig2(p1.x, p1.y), sB = sig2(p1.z, p1.w);
                __half2 gA = __floats2half2_rn(g1.x, g1.y), gB = __floats2half2_rn(g1.z, g1.w);
                __half2 smA = __hmul2(sA, mA), smB = __hmul2(sB, mB);
                aint = __hfma2(smA, gA, __hfma2(smB, gB, aint));
                asii = __hfma2(smA, sA, __hfma2(smB, sB, asii));
                astt = __hfma2(gA, mA, __hfma2(gB, mB, astt));
            }
        }

        float vals[3];
        vals[0] = __low2float(aint) + __high2float(aint);
        vals[1] = __low2float(asii) + __high2float(asii);
        vals[2] = __low2float(astt) + __high2float(astt);
        #pragma unroll
        for (int j = 0; j < 3; j++) {
            #pragma unroll
            for (int o = 16; o; o >>= 1) vals[j] += __shfl_down_sync(0xFFFFFFFFu, vals[j], o);
        }
        if (lane == 0) {
            #pragma unroll
            for (int j = 0; j < 3; j++) sred[wid][j] = vals[j];
        }
        __syncthreads();
        if (t < 3) {
            float s = 0.f;
            #pragma unroll
            for (int ww = 0; ww < 8; ww++) s += sred[ww][t];
            int id = b * NKC + c;
            if (t == 0)      atomicAdd(&g_ki[id],  (double)s);
            else if (t == 1) atomicAdd(&g_kii[id], (double)s);
            else             atomicAdd(&g_ktt[id], (double)s);
        }
    } else {
        // ================= pass2 role: OHEM select for one batch ========
        int b = blk - DICE_BLKS;

        unsigned cnt[CH2];
        int base = t * CH2;
        {
            uint4* hp = reinterpret_cast<uint4*>(&g_hist1[b][0]) + t * 3;
            const uint4 z4 = make_uint4(0u, 0u, 0u, 0u);
            #pragma unroll
            for (int j = 0; j < 3; j++) {
                uint4 q = hp[j];
                cnt[4 * j + 0] = q.x; cnt[4 * j + 1] = q.y;
                cnt[4 * j + 2] = q.z; cnt[4 * j + 3] = q.w;
                hp[j] = z4;   // restore zero for next replay
            }
        }
        unsigned s = 0; float wf = 0.f;
        #pragma unroll
        for (int j = 0; j < CH2; j++) {
            float v = bucket2float(base + j);
            s += cnt[j];
            wf = fmaf((float)cnt[j], v * v, wf);
        }
        double w = (double)wf;

        // warp inclusive suffix scan
        unsigned sv = s; double wv = w;
        #pragma unroll
        for (int off = 1; off < 32; off <<= 1) {
            unsigned s2 = __shfl_down_sync(0xFFFFFFFFu, sv, off);
            double   w2 = __shfl_down_sync(0xFFFFFFFFu, wv, off);
            if (lane + off < 32) { sv += s2; wv += w2; }
        }
        if (lane == 0) { sCntW[wid] = sv; sWW[wid] = wv; }
        __syncthreads();
        if (wid == 0 && lane < 8) {
            unsigned a = sCntW[lane]; double aw = sWW[lane];
            unsigned ai = a; double awi = aw;
            #pragma unroll
            for (int off = 1; off < 8; off <<= 1) {
                unsigned s2 = __shfl_down_sync(0xFFu, ai, off);
                double   w2 = __shfl_down_sync(0xFFu, awi, off);
                if (lane + off < 8) { ai += s2; awi += w2; }
            }
            sCntA[lane] = ai - a;
            sWA[lane]   = awi - aw;
            if (lane == 0) { sTotal = ai; sHard = 0.0; }
        }
        __syncthreads();

        unsigned nneg = sTotal;
        unsigned npos = g_npos[b];
        unsigned k = 3u * npos; if (k > nneg) k = nneg;

        unsigned incl = sv + sCntA[wid];
        unsigned above = incl - s;
        double wincl = wv + sWA[wid];
        double wabove = wincl - w;

        if (k > 0 && above < k && incl >= k) {
            double wacc = wabove;
            unsigned cum = above;
            bool done = false;
            #pragma unroll
            for (int j = CH2 - 1; j >= 0; j--) {
                if (!done) {
                    unsigned c = cnt[j];
                    float v = bucket2float(base + j);
                    double v2 = (double)v * (double)v;
                    if (cum + c >= k) { sHard = wacc + (double)(k - cum) * v2; done = true; }
                    else { cum += c; wacc += (double)c * v2; }
                }
            }
        }
        __syncthreads();

        if (t == 0) {
            double np = (double)npos;
            g_losstext[b] = 1.0 - 2.0 * g_sp[b] / (g_sp2[b] + sHard + np + EPSL);
            g_sp[b] = 0.0; g_sp2[b] = 0.0; g_npos[b] = 0u;
        }
    }

    // ---------- completion counter + epilogue (any role) ----------
    __syncthreads();
    if (t == 0) {
        __threadfence();
        sLast = (atomicAdd(&g_done, 1u) == TOTAL_BLKS - 1);
    }
    __syncthreads();

    if (sLast) {
        double v = 0.0;
        if (t < BATCH * NKC) {
            v = 1.0 - 2.0 * g_ki[t] / (g_kii[t] + g_ktt[t] + EPSL);
            g_ki[t] = 0.0; g_kii[t] = 0.0; g_ktt[t] = 0.0;
        }
        if (t < 128) sd[t] = v;
        __syncthreads();
        #pragma unroll
        for (int o = 64; o; o >>= 1) { if (t < o && t < 128) sd[t] += sd[t + o]; __syncthreads(); }
        double lk = sd[0] / (double)(BATCH * NKC);
        __syncthreads();
        double lt_in = 0.0;
        if (t < BATCH) { lt_in = g_losstext[t]; g_losstext[t] = 0.0; }
        if (t < 128) sd[t] = lt_in;
        __syncthreads();
        #pragma unroll
        for (int o = 64; o; o >>= 1) { if (t < o && t < 128) sd[t] += sd[t + o]; __syncthreads(); }
        if (t == 0) {
            double lt = sd[0] / (double)BATCH;
            out[0] = (float)(lk + 0.5 * lt);
            out[1] = (float)lt;
            out[2] = (float)lk;
            g_done = 0u;
        }
    }
}

// ---------------- launch ----------------
extern "C" void kernel_launch(void* const* d_in, const int* in_sizes, int n_in,
                              void* d_out, int out_size) {
    const float4* pred = (const float4*)d_in[0];
    const float4* gtt  = (const float4*)d_in[1];
    const float4* gtk  = (const float4*)d_in[2];
    const float4* msk  = (const float4*)d_in[3];
    float* out = (float*)d_out;

    text_kernel<<<BATCH * BPB, NT>>>(pred, gtt, msk);
    dice_kernel<<<TOTAL_BLKS, NT>>>(pred, gtk, out);
}